// round 4
// baseline (speedup 1.0000x reference)
#include <cuda_runtime.h>
#include <cuda_bf16.h>

// PoleInteraction, q-fused + receiver-CSR form:
//   p = MLP(LayerNorm(x));  q[n,i,c] = vln[c]*p[n,c]*vec[n,i,c]
//   dx[n,c] = sum_{e: recv(e)=n} sum_ij q[n,i,c]*M[e,i,j]*q[send(e),j,c]

#define NODES_MAX 50000
#define EDGES_MAX 800000
#define CCH 64

__device__ float g_q[NODES_MAX * 3 * CCH];   // fused w*p*vec field [N,3,64]
__device__ int   g_cnt[NODES_MAX];           // histogram / scatter cursor
__device__ int   g_start[NODES_MAX + 1];     // CSR row starts
__device__ int2  g_es[EDGES_MAX];            // (sender, edge_id) sorted by receiver

// ---------------------------------------------------------------------------
// Sort pipeline: zero -> histogram -> scan(+zero cnt) -> scatter
// ---------------------------------------------------------------------------
__global__ void k_zero(int N)
{
    int i = blockIdx.x * blockDim.x + threadIdx.x;
    if (i < N) g_cnt[i] = 0;
}

__global__ void k_hist(const int* __restrict__ receivers, int E)
{
    int e = blockIdx.x * blockDim.x + threadIdx.x;
    if (e < E) atomicAdd(&g_cnt[receivers[e]], 1);
}

// single block, 1024 threads: exclusive scan of g_cnt into g_start, re-zero g_cnt
__global__ __launch_bounds__(1024) void k_scan(int N)
{
    __shared__ int ssum[1024];
    int t = threadIdx.x;
    int ch = (N + 1023) / 1024;
    int base = t * ch;
    int end  = min(base + ch, N);

    int s = 0;
    for (int i = base; i < end; i++) s += g_cnt[i];
    ssum[t] = s;
    __syncthreads();
    for (int off = 1; off < 1024; off <<= 1) {
        int v = (t >= off) ? ssum[t - off] : 0;
        __syncthreads();
        ssum[t] += v;
        __syncthreads();
    }
    int run = ssum[t] - s;   // exclusive prefix
    for (int i = base; i < end; i++) {
        int c = g_cnt[i];
        g_start[i] = run;
        run += c;
        g_cnt[i] = 0;
    }
    if (t == 1023) g_start[N] = ssum[1023];
}

__global__ void k_scatter(const int* __restrict__ senders,
                          const int* __restrict__ receivers, int E)
{
    int e = blockIdx.x * blockDim.x + threadIdx.x;
    if (e >= E) return;
    int r = receivers[e];
    int pos = g_start[r] + atomicAdd(&g_cnt[r], 1);
    g_es[pos] = make_int2(senders[e], e);
}

// ---------------------------------------------------------------------------
// K1: LayerNorm + MLP (64 -> 128 silu -> 64) + q epilogue.
// ---------------------------------------------------------------------------
__global__ __launch_bounds__(256) void k_node(
    const float* __restrict__ x,
    const float* __restrict__ vec,
    const float* __restrict__ ln_s, const float* __restrict__ ln_b,
    const float* __restrict__ vw,
    const float* __restrict__ w1, const float* __restrict__ b1,
    const float* __restrict__ w2, const float* __restrict__ b2,
    int N)
{
    extern __shared__ float sm[];
    float* w1s = sm;                     // 64*128
    float* w2s = w1s + 64 * 128;         // 128*64
    float* xns = w2s + 128 * 64;         // 8 warps * 4 nodes * 64
    float* hs  = xns + 8 * 4 * 64;       // 8 warps * 4 nodes * 128

    int tid = threadIdx.x;
    for (int i = tid; i < (64 * 128) / 4; i += blockDim.x)
        reinterpret_cast<float4*>(w1s)[i] = reinterpret_cast<const float4*>(w1)[i];
    for (int i = tid; i < (128 * 64) / 4; i += blockDim.x)
        reinterpret_cast<float4*>(w2s)[i] = reinterpret_cast<const float4*>(w2)[i];
    __syncthreads();

    int warp = tid >> 5, lane = tid & 31;
    int node0 = (blockIdx.x * 8 + warp) * 4;
    if (node0 >= N) return;
    float* xn = xns + warp * 4 * 64;
    float* hh = hs  + warp * 4 * 128;

    float2 lns = reinterpret_cast<const float2*>(ln_s)[lane];
    float2 lnb = reinterpret_cast<const float2*>(ln_b)[lane];

    #pragma unroll
    for (int u = 0; u < 4; u++) {
        int n = node0 + u;
        float2 v = make_float2(0.f, 0.f);
        if (n < N) v = reinterpret_cast<const float2*>(x + (size_t)n * 64)[lane];
        float s  = v.x + v.y;
        float sq = v.x * v.x + v.y * v.y;
        #pragma unroll
        for (int o = 16; o; o >>= 1) {
            s  += __shfl_xor_sync(0xffffffffu, s,  o);
            sq += __shfl_xor_sync(0xffffffffu, sq, o);
        }
        float mean = s * (1.f / 64.f);
        float var  = sq * (1.f / 64.f) - mean * mean;
        float rstd = rsqrtf(var + 1e-5f);
        float2 o;
        o.x = (v.x - mean) * rstd * lns.x + lnb.x;
        o.y = (v.y - mean) * rstd * lns.y + lnb.y;
        reinterpret_cast<float2*>(xn + u * 64)[lane] = o;
    }
    __syncwarp();

    float4 bb1 = reinterpret_cast<const float4*>(b1)[lane];
    float4 acc0 = bb1, acc1 = bb1, acc2 = bb1, acc3 = bb1;
    #pragma unroll 4
    for (int c = 0; c < 64; c++) {
        float4 w = reinterpret_cast<float4*>(w1s + c * 128)[lane];
        float x0 = xn[0 * 64 + c], x1 = xn[1 * 64 + c];
        float x2 = xn[2 * 64 + c], x3 = xn[3 * 64 + c];
        acc0.x += x0 * w.x; acc0.y += x0 * w.y; acc0.z += x0 * w.z; acc0.w += x0 * w.w;
        acc1.x += x1 * w.x; acc1.y += x1 * w.y; acc1.z += x1 * w.z; acc1.w += x1 * w.w;
        acc2.x += x2 * w.x; acc2.y += x2 * w.y; acc2.z += x2 * w.z; acc2.w += x2 * w.w;
        acc3.x += x3 * w.x; acc3.y += x3 * w.y; acc3.z += x3 * w.z; acc3.w += x3 * w.w;
    }

    {
        float4 a[4] = {acc0, acc1, acc2, acc3};
        #pragma unroll
        for (int u = 0; u < 4; u++) {
            float4 v = a[u];
            v.x = v.x / (1.f + __expf(-v.x));
            v.y = v.y / (1.f + __expf(-v.y));
            v.z = v.z / (1.f + __expf(-v.z));
            v.w = v.w / (1.f + __expf(-v.w));
            reinterpret_cast<float4*>(hh + u * 128)[lane] = v;
        }
    }
    __syncwarp();

    float2 bb2 = reinterpret_cast<const float2*>(b2)[lane];
    float2 p0 = bb2, p1 = bb2, p2 = bb2, p3 = bb2;
    #pragma unroll 4
    for (int k = 0; k < 128; k++) {
        float2 w = reinterpret_cast<float2*>(w2s + k * 64)[lane];
        float h0 = hh[0 * 128 + k], h1 = hh[1 * 128 + k];
        float h2 = hh[2 * 128 + k], h3 = hh[3 * 128 + k];
        p0.x += h0 * w.x; p0.y += h0 * w.y;
        p1.x += h1 * w.x; p1.y += h1 * w.y;
        p2.x += h2 * w.x; p2.y += h2 * w.y;
        p3.x += h3 * w.x; p3.y += h3 * w.y;
    }

    float2 wv = reinterpret_cast<const float2*>(vw)[lane];
    {
        float2 p[4] = {p0, p1, p2, p3};
        #pragma unroll
        for (int u = 0; u < 4; u++) {
            int n = node0 + u;
            if (n >= N) continue;
            float2 pw;
            pw.x = p[u].x * wv.x;
            pw.y = p[u].y * wv.y;
            const float2* vsrc = reinterpret_cast<const float2*>(vec + (size_t)n * 192);
            float2*       qdst = reinterpret_cast<float2*>(g_q + (size_t)n * 192);
            #pragma unroll
            for (int i = 0; i < 3; i++) {
                float2 v = vsrc[i * 32 + lane];
                float2 qq;
                qq.x = pw.x * v.x;
                qq.y = pw.y * v.y;
                qdst[i * 32 + lane] = qq;
            }
        }
    }
}

// ---------------------------------------------------------------------------
// K2: CSR edge phase. 16 lanes per receiver node, lane owns 4 channels.
// qi loaded once per node; M loaded cooperatively (lanes 0-8) + shuffled;
// output written with one plain float4 store (zeros for degree-0 nodes).
// ---------------------------------------------------------------------------
__global__ __launch_bounds__(256) void k_edge_csr(
    const float* __restrict__ Mm,
    float* __restrict__ out,
    int N)
{
    int t = blockIdx.x * blockDim.x + threadIdx.x;
    int n = t >> 4;
    if (n >= N) return;
    int l = t & 15;

    int segA = g_start[n];
    int segB = g_start[n + 1];

    float4 acc = make_float4(0.f, 0.f, 0.f, 0.f);

    if (segA < segB) {
        const float4* qi = reinterpret_cast<const float4*>(g_q + (size_t)n * 192) + l;
        float4 qi0 = __ldg(qi + 0), qi1 = __ldg(qi + 16), qi2 = __ldg(qi + 32);

        for (int k = segA; k < segB; k++) {
            int2 es = __ldg(&g_es[k]);   // uniform across the 16-lane group
            int s = es.x;
            long long e = es.y;

            // cooperative M load: lanes 0..8 fetch the 9 contiguous floats
            float mv = 0.f;
            if (l < 9) mv = __ldg(Mm + e * 9 + l);
            float m00 = __shfl_sync(0xffffffffu, mv, 0, 16);
            float m01 = __shfl_sync(0xffffffffu, mv, 1, 16);
            float m02 = __shfl_sync(0xffffffffu, mv, 2, 16);
            float m10 = __shfl_sync(0xffffffffu, mv, 3, 16);
            float m11 = __shfl_sync(0xffffffffu, mv, 4, 16);
            float m12 = __shfl_sync(0xffffffffu, mv, 5, 16);
            float m20 = __shfl_sync(0xffffffffu, mv, 6, 16);
            float m21 = __shfl_sync(0xffffffffu, mv, 7, 16);
            float m22 = __shfl_sync(0xffffffffu, mv, 8, 16);

            const float4* qj = reinterpret_cast<const float4*>(g_q + (size_t)s * 192) + l;
            float4 qj0 = __ldg(qj + 0), qj1 = __ldg(qj + 16), qj2 = __ldg(qj + 32);

            float4 f0, f1, f2;
            f0.x = m00 * qj0.x + m01 * qj1.x + m02 * qj2.x;
            f0.y = m00 * qj0.y + m01 * qj1.y + m02 * qj2.y;
            f0.z = m00 * qj0.z + m01 * qj1.z + m02 * qj2.z;
            f0.w = m00 * qj0.w + m01 * qj1.w + m02 * qj2.w;
            f1.x = m10 * qj0.x + m11 * qj1.x + m12 * qj2.x;
            f1.y = m10 * qj0.y + m11 * qj1.y + m12 * qj2.y;
            f1.z = m10 * qj0.z + m11 * qj1.z + m12 * qj2.z;
            f1.w = m10 * qj0.w + m11 * qj1.w + m12 * qj2.w;
            f2.x = m20 * qj0.x + m21 * qj1.x + m22 * qj2.x;
            f2.y = m20 * qj0.y + m21 * qj1.y + m22 * qj2.y;
            f2.z = m20 * qj0.z + m21 * qj1.z + m22 * qj2.z;
            f2.w = m20 * qj0.w + m21 * qj1.w + m22 * qj2.w;

            acc.x += qi0.x * f0.x + qi1.x * f1.x + qi2.x * f2.x;
            acc.y += qi0.y * f0.y + qi1.y * f1.y + qi2.y * f2.y;
            acc.z += qi0.z * f0.z + qi1.z * f1.z + qi2.z * f2.z;
            acc.w += qi0.w * f0.w + qi1.w * f1.w + qi2.w * f2.w;
        }
    }

    reinterpret_cast<float4*>(out + (size_t)n * 64)[l] = acc;
}

// ---------------------------------------------------------------------------
extern "C" void kernel_launch(void* const* d_in, const int* in_sizes, int n_in,
                              void* d_out, int out_size)
{
    const float* x         = (const float*)d_in[0];
    const float* vec       = (const float*)d_in[1];
    const int*   senders   = (const int*)  d_in[2];
    const int*   receivers = (const int*)  d_in[3];
    const float* im        = (const float*)d_in[4];
    const float* ln_scale  = (const float*)d_in[5];
    const float* ln_bias   = (const float*)d_in[6];
    const float* vln       = (const float*)d_in[7];
    const float* w1        = (const float*)d_in[8];
    const float* b1        = (const float*)d_in[9];
    const float* w2        = (const float*)d_in[10];
    const float* b2        = (const float*)d_in[11];

    int N = in_sizes[0] / CCH;
    int E = in_sizes[2];

    // CSR build
    k_zero<<<(N + 255) / 256, 256>>>(N);
    k_hist<<<(E + 255) / 256, 256>>>(receivers, E);
    k_scan<<<1, 1024>>>(N);
    k_scatter<<<(E + 255) / 256, 256>>>(senders, receivers, E);

    // node MLP + q
    const int smem = (64 * 128 + 128 * 64 + 8 * 4 * 64 + 8 * 4 * 128) * (int)sizeof(float);
    static bool attr_set = false;
    if (!attr_set) {
        cudaFuncSetAttribute(k_node, cudaFuncAttributeMaxDynamicSharedMemorySize, smem);
        attr_set = true;
    }
    k_node<<<(N + 31) / 32, 256, smem>>>(x, vec, ln_scale, ln_bias, vln, w1, b1, w2, b2, N);

    // CSR edge reduction (writes full output, no memset needed)
    k_edge_csr<<<(N * 16 + 255) / 256, 256>>>(im, (float*)d_out, N);
}

// round 5
// speedup vs baseline: 1.1913x; 1.1913x over previous
#include <cuda_runtime.h>
#include <cuda_bf16.h>

// PoleInteraction, q-fused + receiver-sorted chunked form:
//   p = MLP(LayerNorm(x));  q[n,i,c] = vln[c]*p[n,c]*vec[n,i,c]
//   dx[n,c] = sum_{e: recv(e)=n} sum_ij q[n,i,c]*M[e,i,j]*q[send(e),j,c]
// Edges counting-sorted by receiver; edge kernel walks fixed 8-edge chunks,
// amortizing qi loads and output atomics across same-receiver runs.

#define NODES_MAX 50000
#define EDGES_MAX 800000
#define CCH 64
#define CHUNK 8

__device__ float g_q[NODES_MAX * 3 * CCH];   // fused w*p*vec field [N,3,64]
__device__ int   g_cnt[NODES_MAX];           // histogram / scatter cursor
__device__ int   g_start[NODES_MAX + 1];     // CSR row starts (scatter only)
__device__ int4  g_rec[EDGES_MAX];           // (sender, receiver, edge_id, 0) sorted by receiver

// ---------------------------------------------------------------------------
// CSR build: memset(g_cnt) -> histogram -> scan -> scatter
// ---------------------------------------------------------------------------
__global__ __launch_bounds__(256) void k_hist(const int* __restrict__ receivers, int E)
{
    int e0 = (blockIdx.x * blockDim.x + threadIdx.x) * 4;
    #pragma unroll
    for (int i = 0; i < 4; i++) {
        int e = e0 + i;
        if (e < E) atomicAdd(&g_cnt[__ldg(receivers + e)], 1);
    }
}

// single block, 1024 threads: exclusive scan of g_cnt into g_start, re-zero g_cnt
__global__ __launch_bounds__(1024) void k_scan(int N)
{
    __shared__ int ssum[1024];
    int t = threadIdx.x;
    int ch = (N + 1023) / 1024;
    int base = t * ch;
    int end  = min(base + ch, N);

    int s = 0;
    for (int i = base; i < end; i++) s += g_cnt[i];
    ssum[t] = s;
    __syncthreads();
    for (int off = 1; off < 1024; off <<= 1) {
        int v = (t >= off) ? ssum[t - off] : 0;
        __syncthreads();
        ssum[t] += v;
        __syncthreads();
    }
    int run = ssum[t] - s;   // exclusive prefix
    for (int i = base; i < end; i++) {
        int c = g_cnt[i];
        g_start[i] = run;
        run += c;
        g_cnt[i] = 0;
    }
    if (t == 1023) g_start[N] = ssum[1023];
}

__global__ __launch_bounds__(256) void k_scatter(const int* __restrict__ senders,
                                                 const int* __restrict__ receivers, int E)
{
    int e0 = (blockIdx.x * blockDim.x + threadIdx.x) * 4;
    #pragma unroll
    for (int i = 0; i < 4; i++) {
        int e = e0 + i;
        if (e < E) {
            int r = __ldg(receivers + e);
            int s = __ldg(senders + e);
            int pos = g_start[r] + atomicAdd(&g_cnt[r], 1);
            g_rec[pos] = make_int4(s, r, e, 0);
        }
    }
}

// ---------------------------------------------------------------------------
// K1: LayerNorm + MLP (64 -> 128 silu -> 64) + q epilogue.
// ---------------------------------------------------------------------------
__global__ __launch_bounds__(256) void k_node(
    const float* __restrict__ x,
    const float* __restrict__ vec,
    const float* __restrict__ ln_s, const float* __restrict__ ln_b,
    const float* __restrict__ vw,
    const float* __restrict__ w1, const float* __restrict__ b1,
    const float* __restrict__ w2, const float* __restrict__ b2,
    int N)
{
    extern __shared__ float sm[];
    float* w1s = sm;                     // 64*128
    float* w2s = w1s + 64 * 128;         // 128*64
    float* xns = w2s + 128 * 64;         // 8 warps * 4 nodes * 64
    float* hs  = xns + 8 * 4 * 64;       // 8 warps * 4 nodes * 128

    int tid = threadIdx.x;
    for (int i = tid; i < (64 * 128) / 4; i += blockDim.x)
        reinterpret_cast<float4*>(w1s)[i] = reinterpret_cast<const float4*>(w1)[i];
    for (int i = tid; i < (128 * 64) / 4; i += blockDim.x)
        reinterpret_cast<float4*>(w2s)[i] = reinterpret_cast<const float4*>(w2)[i];
    __syncthreads();

    int warp = tid >> 5, lane = tid & 31;
    int node0 = (blockIdx.x * 8 + warp) * 4;
    if (node0 >= N) return;
    float* xn = xns + warp * 4 * 64;
    float* hh = hs  + warp * 4 * 128;

    float2 lns = reinterpret_cast<const float2*>(ln_s)[lane];
    float2 lnb = reinterpret_cast<const float2*>(ln_b)[lane];

    #pragma unroll
    for (int u = 0; u < 4; u++) {
        int n = node0 + u;
        float2 v = make_float2(0.f, 0.f);
        if (n < N) v = reinterpret_cast<const float2*>(x + (size_t)n * 64)[lane];
        float s  = v.x + v.y;
        float sq = v.x * v.x + v.y * v.y;
        #pragma unroll
        for (int o = 16; o; o >>= 1) {
            s  += __shfl_xor_sync(0xffffffffu, s,  o);
            sq += __shfl_xor_sync(0xffffffffu, sq, o);
        }
        float mean = s * (1.f / 64.f);
        float var  = sq * (1.f / 64.f) - mean * mean;
        float rstd = rsqrtf(var + 1e-5f);
        float2 o;
        o.x = (v.x - mean) * rstd * lns.x + lnb.x;
        o.y = (v.y - mean) * rstd * lns.y + lnb.y;
        reinterpret_cast<float2*>(xn + u * 64)[lane] = o;
    }
    __syncwarp();

    float4 bb1 = reinterpret_cast<const float4*>(b1)[lane];
    float4 acc0 = bb1, acc1 = bb1, acc2 = bb1, acc3 = bb1;
    #pragma unroll 4
    for (int c = 0; c < 64; c++) {
        float4 w = reinterpret_cast<float4*>(w1s + c * 128)[lane];
        float x0 = xn[0 * 64 + c], x1 = xn[1 * 64 + c];
        float x2 = xn[2 * 64 + c], x3 = xn[3 * 64 + c];
        acc0.x += x0 * w.x; acc0.y += x0 * w.y; acc0.z += x0 * w.z; acc0.w += x0 * w.w;
        acc1.x += x1 * w.x; acc1.y += x1 * w.y; acc1.z += x1 * w.z; acc1.w += x1 * w.w;
        acc2.x += x2 * w.x; acc2.y += x2 * w.y; acc2.z += x2 * w.z; acc2.w += x2 * w.w;
        acc3.x += x3 * w.x; acc3.y += x3 * w.y; acc3.z += x3 * w.z; acc3.w += x3 * w.w;
    }

    {
        float4 a[4] = {acc0, acc1, acc2, acc3};
        #pragma unroll
        for (int u = 0; u < 4; u++) {
            float4 v = a[u];
            v.x = v.x / (1.f + __expf(-v.x));
            v.y = v.y / (1.f + __expf(-v.y));
            v.z = v.z / (1.f + __expf(-v.z));
            v.w = v.w / (1.f + __expf(-v.w));
            reinterpret_cast<float4*>(hh + u * 128)[lane] = v;
        }
    }
    __syncwarp();

    float2 bb2 = reinterpret_cast<const float2*>(b2)[lane];
    float2 p0 = bb2, p1 = bb2, p2 = bb2, p3 = bb2;
    #pragma unroll 4
    for (int k = 0; k < 128; k++) {
        float2 w = reinterpret_cast<float2*>(w2s + k * 64)[lane];
        float h0 = hh[0 * 128 + k], h1 = hh[1 * 128 + k];
        float h2 = hh[2 * 128 + k], h3 = hh[3 * 128 + k];
        p0.x += h0 * w.x; p0.y += h0 * w.y;
        p1.x += h1 * w.x; p1.y += h1 * w.y;
        p2.x += h2 * w.x; p2.y += h2 * w.y;
        p3.x += h3 * w.x; p3.y += h3 * w.y;
    }

    float2 wv = reinterpret_cast<const float2*>(vw)[lane];
    {
        float2 p[4] = {p0, p1, p2, p3};
        #pragma unroll
        for (int u = 0; u < 4; u++) {
            int n = node0 + u;
            if (n >= N) continue;
            float2 pw;
            pw.x = p[u].x * wv.x;
            pw.y = p[u].y * wv.y;
            const float2* vsrc = reinterpret_cast<const float2*>(vec + (size_t)n * 192);
            float2*       qdst = reinterpret_cast<float2*>(g_q + (size_t)n * 192);
            #pragma unroll
            for (int i = 0; i < 3; i++) {
                float2 v = vsrc[i * 32 + lane];
                float2 qq;
                qq.x = pw.x * v.x;
                qq.y = pw.y * v.y;
                qdst[i * 32 + lane] = qq;
            }
        }
    }
}

// ---------------------------------------------------------------------------
// K2: chunked edge phase over receiver-sorted edges.
// 16 lanes per 8-edge chunk; lane owns 4 channels. qi + output flush amortized
// over same-receiver runs; flush via red.v4 (out pre-zeroed).
// ---------------------------------------------------------------------------
__global__ __launch_bounds__(256) void k_edge_chunk(
    const float* __restrict__ Mm,
    float* __restrict__ out,
    int E)
{
    int t = blockIdx.x * blockDim.x + threadIdx.x;
    int g = t >> 4;
    int l = t & 15;
    int base = g * CHUNK;
    if (base >= E) return;
    int cnt = min(CHUNK, E - base);

    float4 acc = make_float4(0.f, 0.f, 0.f, 0.f);
    float4 qi0, qi1, qi2;
    int cur_r = -1;

    for (int k = 0; k < cnt; k++) {
        int4 rec = __ldg(&g_rec[base + k]);   // uniform across 16-lane group

        if (rec.y != cur_r) {
            if (cur_r >= 0) {
                float* dst = out + (size_t)cur_r * 64 + 4 * l;
                asm volatile("red.global.add.v4.f32 [%0], {%1, %2, %3, %4};"
                             :: "l"(dst), "f"(acc.x), "f"(acc.y), "f"(acc.z), "f"(acc.w)
                             : "memory");
            }
            cur_r = rec.y;
            const float4* qi = reinterpret_cast<const float4*>(g_q + (size_t)cur_r * 192) + l;
            qi0 = __ldg(qi + 0); qi1 = __ldg(qi + 16); qi2 = __ldg(qi + 32);
            acc = make_float4(0.f, 0.f, 0.f, 0.f);
        }

        long long e = rec.z;
        const float* M = Mm + e * 9;
        float m00 = __ldg(M + 0), m01 = __ldg(M + 1), m02 = __ldg(M + 2);
        float m10 = __ldg(M + 3), m11 = __ldg(M + 4), m12 = __ldg(M + 5);
        float m20 = __ldg(M + 6), m21 = __ldg(M + 7), m22 = __ldg(M + 8);

        const float4* qj = reinterpret_cast<const float4*>(g_q + (size_t)rec.x * 192) + l;
        float4 qj0 = __ldg(qj + 0), qj1 = __ldg(qj + 16), qj2 = __ldg(qj + 32);

        float4 f0, f1, f2;
        f0.x = m00 * qj0.x + m01 * qj1.x + m02 * qj2.x;
        f0.y = m00 * qj0.y + m01 * qj1.y + m02 * qj2.y;
        f0.z = m00 * qj0.z + m01 * qj1.z + m02 * qj2.z;
        f0.w = m00 * qj0.w + m01 * qj1.w + m02 * qj2.w;
        f1.x = m10 * qj0.x + m11 * qj1.x + m12 * qj2.x;
        f1.y = m10 * qj0.y + m11 * qj1.y + m12 * qj2.y;
        f1.z = m10 * qj0.z + m11 * qj1.z + m12 * qj2.z;
        f1.w = m10 * qj0.w + m11 * qj1.w + m12 * qj2.w;
        f2.x = m20 * qj0.x + m21 * qj1.x + m22 * qj2.x;
        f2.y = m20 * qj0.y + m21 * qj1.y + m22 * qj2.y;
        f2.z = m20 * qj0.z + m21 * qj1.z + m22 * qj2.z;
        f2.w = m20 * qj0.w + m21 * qj1.w + m22 * qj2.w;

        acc.x += qi0.x * f0.x + qi1.x * f1.x + qi2.x * f2.x;
        acc.y += qi0.y * f0.y + qi1.y * f1.y + qi2.y * f2.y;
        acc.z += qi0.z * f0.z + qi1.z * f1.z + qi2.z * f2.z;
        acc.w += qi0.w * f0.w + qi1.w * f1.w + qi2.w * f2.w;
    }

    {
        float* dst = out + (size_t)cur_r * 64 + 4 * l;
        asm volatile("red.global.add.v4.f32 [%0], {%1, %2, %3, %4};"
                     :: "l"(dst), "f"(acc.x), "f"(acc.y), "f"(acc.z), "f"(acc.w)
                     : "memory");
    }
}

// ---------------------------------------------------------------------------
extern "C" void kernel_launch(void* const* d_in, const int* in_sizes, int n_in,
                              void* d_out, int out_size)
{
    const float* x         = (const float*)d_in[0];
    const float* vec       = (const float*)d_in[1];
    const int*   senders   = (const int*)  d_in[2];
    const int*   receivers = (const int*)  d_in[3];
    const float* im        = (const float*)d_in[4];
    const float* ln_scale  = (const float*)d_in[5];
    const float* ln_bias   = (const float*)d_in[6];
    const float* vln       = (const float*)d_in[7];
    const float* w1        = (const float*)d_in[8];
    const float* b1        = (const float*)d_in[9];
    const float* w2        = (const float*)d_in[10];
    const float* b2        = (const float*)d_in[11];

    int N = in_sizes[0] / CCH;
    int E = in_sizes[2];

    const int smem = (64 * 128 + 128 * 64 + 8 * 4 * 64 + 8 * 4 * 128) * (int)sizeof(float);
    static void* cnt_ptr = nullptr;
    if (!cnt_ptr) {
        cudaFuncSetAttribute(k_node, cudaFuncAttributeMaxDynamicSharedMemorySize, smem);
        cudaGetSymbolAddress(&cnt_ptr, g_cnt);
    }

    // zero outputs + histogram counters
    cudaMemsetAsync(d_out, 0, (size_t)out_size * sizeof(float));
    cudaMemsetAsync(cnt_ptr, 0, (size_t)N * sizeof(int));

    // CSR build (4 edges/thread for ILP)
    int e4blocks = (E + 4 * 256 - 1) / (4 * 256);
    k_hist<<<e4blocks, 256>>>(receivers, E);
    k_scan<<<1, 1024>>>(N);
    k_scatter<<<e4blocks, 256>>>(senders, receivers, E);

    // node MLP + q
    k_node<<<(N + 31) / 32, 256, smem>>>(x, vec, ln_scale, ln_bias, vln, w1, b1, w2, b2, N);

    // chunked edge reduction
    int nchunks = (E + CHUNK - 1) / CHUNK;
    long long tthreads = (long long)nchunks * 16;
    int eblocks = (int)((tthreads + 255) / 256);
    k_edge_chunk<<<eblocks, 256>>>(im, (float*)d_out, E);
}

// round 6
// speedup vs baseline: 1.8051x; 1.5153x over previous
#include <cuda_runtime.h>
#include <cuda_bf16.h>

// PoleInteraction, q-fused form (R2 skeleton + smem/ldg tuning):
//   p = MLP(LayerNorm(x));  q[n,i,c] = vln[c]*p[n,c]*vec[n,i,c]
//   dEnergy[e,c] = sum_ij q[r,i,c]*M[e,i,j]*q[s,j,c]
//   dx = segment_sum(dEnergy, receivers)   (red.global.add.v4)

#define NODES_MAX 50000
#define CCH 64

__device__ float g_q[NODES_MAX * 3 * CCH];  // fused w*p*vec field [N,3,64]

// ---------------------------------------------------------------------------
// K1: LayerNorm + MLP (64 -> 128 silu -> 64) + q epilogue.
// Warp per 4 nodes. x staged TRANSPOSED [c][node] so layer1 reads one
// broadcast LDS128 per channel; layer2 steps k by 4 reading h via broadcast
// LDS128 -> smem crossbar drops below the FMA floor.
// ---------------------------------------------------------------------------
__global__ __launch_bounds__(256) void k_node(
    const float* __restrict__ x,
    const float* __restrict__ vec,
    const float* __restrict__ ln_s, const float* __restrict__ ln_b,
    const float* __restrict__ vw,
    const float* __restrict__ w1, const float* __restrict__ b1,
    const float* __restrict__ w2, const float* __restrict__ b2,
    int N)
{
    extern __shared__ float sm[];
    float* w1s = sm;                     // 64*128
    float* w2s = w1s + 64 * 128;         // 128*64
    float* xts = w2s + 128 * 64;         // 8 warps * 64 ch * 4 nodes (transposed)
    float* hs  = xts + 8 * 64 * 4;       // 8 warps * 4 nodes * 128

    int tid = threadIdx.x;
    for (int i = tid; i < (64 * 128) / 4; i += blockDim.x)
        reinterpret_cast<float4*>(w1s)[i] = reinterpret_cast<const float4*>(w1)[i];
    for (int i = tid; i < (128 * 64) / 4; i += blockDim.x)
        reinterpret_cast<float4*>(w2s)[i] = reinterpret_cast<const float4*>(w2)[i];
    __syncthreads();

    int warp = tid >> 5, lane = tid & 31;
    int node0 = (blockIdx.x * 8 + warp) * 4;
    if (node0 >= N) return;
    float* xt = xts + warp * 64 * 4;     // xt[c*4 + u]
    float* hh = hs  + warp * 4 * 128;    // hh[u*128 + k]

    float2 lns = reinterpret_cast<const float2*>(ln_s)[lane];
    float2 lnb = reinterpret_cast<const float2*>(ln_b)[lane];

    // LayerNorm for 4 nodes; thread owns channels 2*lane, 2*lane+1.
    // Store transposed: xt[c*4 + u].
    #pragma unroll
    for (int u = 0; u < 4; u++) {
        int n = node0 + u;
        float2 v = make_float2(0.f, 0.f);
        if (n < N) v = reinterpret_cast<const float2*>(x + (size_t)n * 64)[lane];
        float s  = v.x + v.y;
        float sq = v.x * v.x + v.y * v.y;
        #pragma unroll
        for (int o = 16; o; o >>= 1) {
            s  += __shfl_xor_sync(0xffffffffu, s,  o);
            sq += __shfl_xor_sync(0xffffffffu, sq, o);
        }
        float mean = s * (1.f / 64.f);
        float var  = sq * (1.f / 64.f) - mean * mean;
        float rstd = rsqrtf(var + 1e-5f);
        xt[(2 * lane    ) * 4 + u] = (v.x - mean) * rstd * lns.x + lnb.x;
        xt[(2 * lane + 1) * 4 + u] = (v.y - mean) * rstd * lns.y + lnb.y;
    }
    __syncwarp();

    // Layer 1: thread computes h[4*lane..4*lane+3] for 4 nodes.
    // Per c: one broadcast LDS128 (x of all 4 nodes) + one LDS128 (weights).
    float4 bb1 = reinterpret_cast<const float4*>(b1)[lane];
    float4 acc0 = bb1, acc1 = bb1, acc2 = bb1, acc3 = bb1;
    #pragma unroll 4
    for (int c = 0; c < 64; c++) {
        float4 xv = reinterpret_cast<float4*>(xt)[c];           // nodes 0..3 @ channel c
        float4 w  = reinterpret_cast<float4*>(w1s + c * 128)[lane];
        acc0.x += xv.x * w.x; acc0.y += xv.x * w.y; acc0.z += xv.x * w.z; acc0.w += xv.x * w.w;
        acc1.x += xv.y * w.x; acc1.y += xv.y * w.y; acc1.z += xv.y * w.z; acc1.w += xv.y * w.w;
        acc2.x += xv.z * w.x; acc2.y += xv.z * w.y; acc2.z += xv.z * w.z; acc2.w += xv.z * w.w;
        acc3.x += xv.w * w.x; acc3.y += xv.w * w.y; acc3.z += xv.w * w.z; acc3.w += xv.w * w.w;
    }

    // silu + stage h (vectorized, conflict-free)
    {
        float4 a[4] = {acc0, acc1, acc2, acc3};
        #pragma unroll
        for (int u = 0; u < 4; u++) {
            float4 v = a[u];
            v.x = v.x / (1.f + __expf(-v.x));
            v.y = v.y / (1.f + __expf(-v.y));
            v.z = v.z / (1.f + __expf(-v.z));
            v.w = v.w / (1.f + __expf(-v.w));
            reinterpret_cast<float4*>(hh + u * 128)[lane] = v;
        }
    }
    __syncwarp();

    // Layer 2: thread computes p[2*lane], p[2*lane+1] for 4 nodes.
    // k stepped by 4: h read as broadcast LDS128 per node.
    float2 bb2 = reinterpret_cast<const float2*>(b2)[lane];
    float2 p0 = bb2, p1 = bb2, p2 = bb2, p3 = bb2;
    #pragma unroll 2
    for (int k4 = 0; k4 < 32; k4++) {
        float4 h0 = reinterpret_cast<float4*>(hh + 0 * 128)[k4];
        float4 h1 = reinterpret_cast<float4*>(hh + 1 * 128)[k4];
        float4 h2 = reinterpret_cast<float4*>(hh + 2 * 128)[k4];
        float4 h3 = reinterpret_cast<float4*>(hh + 3 * 128)[k4];
        #pragma unroll
        for (int j = 0; j < 4; j++) {
            float2 w = reinterpret_cast<float2*>(w2s + (4 * k4 + j) * 64)[lane];
            float a0 = (j == 0) ? h0.x : (j == 1) ? h0.y : (j == 2) ? h0.z : h0.w;
            float a1 = (j == 0) ? h1.x : (j == 1) ? h1.y : (j == 2) ? h1.z : h1.w;
            float a2 = (j == 0) ? h2.x : (j == 1) ? h2.y : (j == 2) ? h2.z : h2.w;
            float a3 = (j == 0) ? h3.x : (j == 1) ? h3.y : (j == 2) ? h3.z : h3.w;
            p0.x += a0 * w.x; p0.y += a0 * w.y;
            p1.x += a1 * w.x; p1.y += a1 * w.y;
            p2.x += a2 * w.x; p2.y += a2 * w.y;
            p3.x += a3 * w.x; p3.y += a3 * w.y;
        }
    }

    // Epilogue: q[n,i,c] = vln[c] * p[n,c] * vec[n,i,c]
    float2 wv = reinterpret_cast<const float2*>(vw)[lane];
    {
        float2 p[4] = {p0, p1, p2, p3};
        #pragma unroll
        for (int u = 0; u < 4; u++) {
            int n = node0 + u;
            if (n >= N) continue;
            float2 pw;
            pw.x = p[u].x * wv.x;
            pw.y = p[u].y * wv.y;
            const float2* vsrc = reinterpret_cast<const float2*>(vec + (size_t)n * 192);
            float2*       qdst = reinterpret_cast<float2*>(g_q + (size_t)n * 192);
            #pragma unroll
            for (int i = 0; i < 3; i++) {
                float2 v = vsrc[i * 32 + lane];
                float2 qq;
                qq.x = pw.x * v.x;
                qq.y = pw.y * v.y;
                qdst[i * 32 + lane] = qq;
            }
        }
    }
}

// ---------------------------------------------------------------------------
// K2: per-edge phase. 16 lanes/edge, lane owns 4 channels.
// M loaded cooperatively by lanes 0..8 (1-2 wavefronts) + independent width-16
// shuffles (parallel edges -> latency hidden), instead of 9 uniform LDGs.
// ---------------------------------------------------------------------------
__global__ __launch_bounds__(256) void k_edge(
    const int*   __restrict__ senders,
    const int*   __restrict__ receivers,
    const float* __restrict__ Mm,
    float* __restrict__ out,
    int E)
{
    int t = blockIdx.x * blockDim.x + threadIdx.x;
    int e = t >> 4;
    if (e >= E) return;
    int l = t & 15;

    int s = __ldg(senders + e);
    int r = __ldg(receivers + e);

    // cooperative M load + width-16 broadcast shuffles (all independent)
    float mv = 0.f;
    if (l < 9) mv = __ldg(Mm + (size_t)e * 9 + l);
    float m00 = __shfl_sync(0xffffffffu, mv, 0, 16);
    float m01 = __shfl_sync(0xffffffffu, mv, 1, 16);
    float m02 = __shfl_sync(0xffffffffu, mv, 2, 16);
    float m10 = __shfl_sync(0xffffffffu, mv, 3, 16);
    float m11 = __shfl_sync(0xffffffffu, mv, 4, 16);
    float m12 = __shfl_sync(0xffffffffu, mv, 5, 16);
    float m20 = __shfl_sync(0xffffffffu, mv, 6, 16);
    float m21 = __shfl_sync(0xffffffffu, mv, 7, 16);
    float m22 = __shfl_sync(0xffffffffu, mv, 8, 16);

    const float4* qj = reinterpret_cast<const float4*>(g_q + (size_t)s * 192) + l;
    const float4* qi = reinterpret_cast<const float4*>(g_q + (size_t)r * 192) + l;
    float4 qj0 = __ldg(qj + 0), qj1 = __ldg(qj + 16), qj2 = __ldg(qj + 32);
    float4 qi0 = __ldg(qi + 0), qi1 = __ldg(qi + 16), qi2 = __ldg(qi + 32);

    float4 f0, f1, f2, d;
    f0.x = m00 * qj0.x + m01 * qj1.x + m02 * qj2.x;
    f0.y = m00 * qj0.y + m01 * qj1.y + m02 * qj2.y;
    f0.z = m00 * qj0.z + m01 * qj1.z + m02 * qj2.z;
    f0.w = m00 * qj0.w + m01 * qj1.w + m02 * qj2.w;
    f1.x = m10 * qj0.x + m11 * qj1.x + m12 * qj2.x;
    f1.y = m10 * qj0.y + m11 * qj1.y + m12 * qj2.y;
    f1.z = m10 * qj0.z + m11 * qj1.z + m12 * qj2.z;
    f1.w = m10 * qj0.w + m11 * qj1.w + m12 * qj2.w;
    f2.x = m20 * qj0.x + m21 * qj1.x + m22 * qj2.x;
    f2.y = m20 * qj0.y + m21 * qj1.y + m22 * qj2.y;
    f2.z = m20 * qj0.z + m21 * qj1.z + m22 * qj2.z;
    f2.w = m20 * qj0.w + m21 * qj1.w + m22 * qj2.w;

    d.x = qi0.x * f0.x + qi1.x * f1.x + qi2.x * f2.x;
    d.y = qi0.y * f0.y + qi1.y * f1.y + qi2.y * f2.y;
    d.z = qi0.z * f0.z + qi1.z * f1.z + qi2.z * f2.z;
    d.w = qi0.w * f0.w + qi1.w * f1.w + qi2.w * f2.w;

    float* dst = out + (size_t)r * 64 + 4 * l;
    asm volatile("red.global.add.v4.f32 [%0], {%1, %2, %3, %4};"
                 :: "l"(dst), "f"(d.x), "f"(d.y), "f"(d.z), "f"(d.w)
                 : "memory");
}

// ---------------------------------------------------------------------------
extern "C" void kernel_launch(void* const* d_in, const int* in_sizes, int n_in,
                              void* d_out, int out_size)
{
    const float* x         = (const float*)d_in[0];
    const float* vec       = (const float*)d_in[1];
    const int*   senders   = (const int*)  d_in[2];
    const int*   receivers = (const int*)  d_in[3];
    const float* im        = (const float*)d_in[4];
    const float* ln_scale  = (const float*)d_in[5];
    const float* ln_bias   = (const float*)d_in[6];
    const float* vln       = (const float*)d_in[7];
    const float* w1        = (const float*)d_in[8];
    const float* b1        = (const float*)d_in[9];
    const float* w2        = (const float*)d_in[10];
    const float* b2        = (const float*)d_in[11];

    int N = in_sizes[0] / CCH;
    int E = in_sizes[2];

    cudaMemsetAsync(d_out, 0, (size_t)out_size * sizeof(float));

    const int smem = (64 * 128 + 128 * 64 + 8 * 64 * 4 + 8 * 4 * 128) * (int)sizeof(float);
    static bool attr_set = false;
    if (!attr_set) {
        cudaFuncSetAttribute(k_node, cudaFuncAttributeMaxDynamicSharedMemorySize, smem);
        attr_set = true;
    }
    k_node<<<(N + 31) / 32, 256, smem>>>(x, vec, ln_scale, ln_bias, vln, w1, b1, w2, b2, N);

    long long tot = (long long)E * 16;
    int eblocks = (int)((tot + 255) / 256);
    k_edge<<<eblocks, 256>>>(senders, receivers, im, (float*)d_out, E);
}

// round 9
// speedup vs baseline: 2.0070x; 1.1119x over previous
#include <cuda_runtime.h>
#include <cuda_bf16.h>

// PoleInteraction, q-fused form:
//   p = MLP(LayerNorm(x));  q[n,i,c] = vln[c]*p[n,c]*vec[n,i,c]
//   dEnergy[e,c] = sum_ij q[r,i,c]*M[e,i,j]*q[s,j,c]
//   dx = segment_sum(dEnergy, receivers)   (red.global.add.v4)

#define NODES_MAX 50000
#define CCH 64
#define K1_WARPS 16   // 512-thread blocks: weights amortized over 2x warps -> occ 50%

__device__ float g_q[NODES_MAX * 3 * CCH];  // fused w*p*vec field [N,3,64]

// ---------------------------------------------------------------------------
// K1: LayerNorm + MLP (64 -> 128 silu -> 64) + q epilogue.
// Warp per 4 nodes; 16 warps/block share one smem copy of the weights.
// x staged transposed [c][node]; h read back via broadcast LDS128.
// ---------------------------------------------------------------------------
__global__ __launch_bounds__(32 * K1_WARPS) void k_node(
    const float* __restrict__ x,
    const float* __restrict__ vec,
    const float* __restrict__ ln_s, const float* __restrict__ ln_b,
    const float* __restrict__ vw,
    const float* __restrict__ w1, const float* __restrict__ b1,
    const float* __restrict__ w2, const float* __restrict__ b2,
    int N)
{
    extern __shared__ float sm[];
    float* w1s = sm;                         // 64*128
    float* w2s = w1s + 64 * 128;             // 128*64
    float* xts = w2s + 128 * 64;             // K1_WARPS * 64 ch * 4 nodes (transposed)
    float* hs  = xts + K1_WARPS * 64 * 4;    // K1_WARPS * 4 nodes * 128

    int tid = threadIdx.x;
    for (int i = tid; i < (64 * 128) / 4; i += blockDim.x)
        reinterpret_cast<float4*>(w1s)[i] = reinterpret_cast<const float4*>(w1)[i];
    for (int i = tid; i < (128 * 64) / 4; i += blockDim.x)
        reinterpret_cast<float4*>(w2s)[i] = reinterpret_cast<const float4*>(w2)[i];
    __syncthreads();

    int warp = tid >> 5, lane = tid & 31;
    int node0 = (blockIdx.x * K1_WARPS + warp) * 4;
    if (node0 >= N) return;
    float* xt = xts + warp * 64 * 4;     // xt[c*4 + u]
    float* hh = hs  + warp * 4 * 128;    // hh[u*128 + k]

    float2 lns = reinterpret_cast<const float2*>(ln_s)[lane];
    float2 lnb = reinterpret_cast<const float2*>(ln_b)[lane];

    // LayerNorm for 4 nodes; thread owns channels 2*lane, 2*lane+1.
    #pragma unroll
    for (int u = 0; u < 4; u++) {
        int n = node0 + u;
        float2 v = make_float2(0.f, 0.f);
        if (n < N) v = reinterpret_cast<const float2*>(x + (size_t)n * 64)[lane];
        float s  = v.x + v.y;
        float sq = v.x * v.x + v.y * v.y;
        #pragma unroll
        for (int o = 16; o; o >>= 1) {
            s  += __shfl_xor_sync(0xffffffffu, s,  o);
            sq += __shfl_xor_sync(0xffffffffu, sq, o);
        }
        float mean = s * (1.f / 64.f);
        float var  = sq * (1.f / 64.f) - mean * mean;
        float rstd = rsqrtf(var + 1e-5f);
        xt[(2 * lane    ) * 4 + u] = (v.x - mean) * rstd * lns.x + lnb.x;
        xt[(2 * lane + 1) * 4 + u] = (v.y - mean) * rstd * lns.y + lnb.y;
    }
    __syncwarp();

    // Layer 1: thread computes h[4*lane..4*lane+3] for 4 nodes.
    float4 bb1 = reinterpret_cast<const float4*>(b1)[lane];
    float4 acc0 = bb1, acc1 = bb1, acc2 = bb1, acc3 = bb1;
    #pragma unroll 4
    for (int c = 0; c < 64; c++) {
        float4 xv = reinterpret_cast<float4*>(xt)[c];           // nodes 0..3 @ channel c
        float4 w  = reinterpret_cast<float4*>(w1s + c * 128)[lane];
        acc0.x += xv.x * w.x; acc0.y += xv.x * w.y; acc0.z += xv.x * w.z; acc0.w += xv.x * w.w;
        acc1.x += xv.y * w.x; acc1.y += xv.y * w.y; acc1.z += xv.y * w.z; acc1.w += xv.y * w.w;
        acc2.x += xv.z * w.x; acc2.y += xv.z * w.y; acc2.z += xv.z * w.z; acc2.w += xv.z * w.w;
        acc3.x += xv.w * w.x; acc3.y += xv.w * w.y; acc3.z += xv.w * w.z; acc3.w += xv.w * w.w;
    }

    // silu + stage h
    {
        float4 a[4] = {acc0, acc1, acc2, acc3};
        #pragma unroll
        for (int u = 0; u < 4; u++) {
            float4 v = a[u];
            v.x = v.x / (1.f + __expf(-v.x));
            v.y = v.y / (1.f + __expf(-v.y));
            v.z = v.z / (1.f + __expf(-v.z));
            v.w = v.w / (1.f + __expf(-v.w));
            reinterpret_cast<float4*>(hh + u * 128)[lane] = v;
        }
    }
    __syncwarp();

    // Layer 2: thread computes p[2*lane], p[2*lane+1] for 4 nodes.
    float2 bb2 = reinterpret_cast<const float2*>(b2)[lane];
    float2 p0 = bb2, p1 = bb2, p2 = bb2, p3 = bb2;
    #pragma unroll 2
    for (int k4 = 0; k4 < 32; k4++) {
        float4 h0 = reinterpret_cast<float4*>(hh + 0 * 128)[k4];
        float4 h1 = reinterpret_cast<float4*>(hh + 1 * 128)[k4];
        float4 h2 = reinterpret_cast<float4*>(hh + 2 * 128)[k4];
        float4 h3 = reinterpret_cast<float4*>(hh + 3 * 128)[k4];
        #pragma unroll
        for (int j = 0; j < 4; j++) {
            float2 w = reinterpret_cast<float2*>(w2s + (4 * k4 + j) * 64)[lane];
            float a0 = (j == 0) ? h0.x : (j == 1) ? h0.y : (j == 2) ? h0.z : h0.w;
            float a1 = (j == 0) ? h1.x : (j == 1) ? h1.y : (j == 2) ? h1.z : h1.w;
            float a2 = (j == 0) ? h2.x : (j == 1) ? h2.y : (j == 2) ? h2.z : h2.w;
            float a3 = (j == 0) ? h3.x : (j == 1) ? h3.y : (j == 2) ? h3.z : h3.w;
            p0.x += a0 * w.x; p0.y += a0 * w.y;
            p1.x += a1 * w.x; p1.y += a1 * w.y;
            p2.x += a2 * w.x; p2.y += a2 * w.y;
            p3.x += a3 * w.x; p3.y += a3 * w.y;
        }
    }

    // Epilogue: q[n,i,c] = vln[c] * p[n,c] * vec[n,i,c]
    float2 wv = reinterpret_cast<const float2*>(vw)[lane];
    {
        float2 p[4] = {p0, p1, p2, p3};
        #pragma unroll
        for (int u = 0; u < 4; u++) {
            int n = node0 + u;
            if (n >= N) continue;
            float2 pw;
            pw.x = p[u].x * wv.x;
            pw.y = p[u].y * wv.y;
            const float2* vsrc = reinterpret_cast<const float2*>(vec + (size_t)n * 192);
            float2*       qdst = reinterpret_cast<float2*>(g_q + (size_t)n * 192);
            #pragma unroll
            for (int i = 0; i < 3; i++) {
                float2 v = vsrc[i * 32 + lane];
                float2 qq;
                qq.x = pw.x * v.x;
                qq.y = pw.y * v.y;
                qdst[i * 32 + lane] = qq;
            }
        }
    }
}

// ---------------------------------------------------------------------------
// K2: per-edge phase. 16 lanes/edge, lane owns 4 channels.
// M loaded cooperatively by lanes 0..8 + width-16 broadcast shuffles.
// ---------------------------------------------------------------------------
__global__ __launch_bounds__(256) void k_edge(
    const int*   __restrict__ senders,
    const int*   __restrict__ receivers,
    const float* __restrict__ Mm,
    float* __restrict__ out,
    int E)
{
    int t = blockIdx.x * blockDim.x + threadIdx.x;
    int e = t >> 4;
    if (e >= E) return;
    int l = t & 15;

    int s = __ldg(senders + e);
    int r = __ldg(receivers + e);

    float mv = 0.f;
    if (l < 9) mv = __ldg(Mm + (size_t)e * 9 + l);
    float m00 = __shfl_sync(0xffffffffu, mv, 0, 16);
    float m01 = __shfl_sync(0xffffffffu, mv, 1, 16);
    float m02 = __shfl_sync(0xffffffffu, mv, 2, 16);
    float m10 = __shfl_sync(0xffffffffu, mv, 3, 16);
    float m11 = __shfl_sync(0xffffffffu, mv, 4, 16);
    float m12 = __shfl_sync(0xffffffffu, mv, 5, 16);
    float m20 = __shfl_sync(0xffffffffu, mv, 6, 16);
    float m21 = __shfl_sync(0xffffffffu, mv, 7, 16);
    float m22 = __shfl_sync(0xffffffffu, mv, 8, 16);

    const float4* qj = reinterpret_cast<const float4*>(g_q + (size_t)s * 192) + l;
    const float4* qi = reinterpret_cast<const float4*>(g_q + (size_t)r * 192) + l;
    float4 qj0 = __ldg(qj + 0), qj1 = __ldg(qj + 16), qj2 = __ldg(qj + 32);
    float4 qi0 = __ldg(qi + 0), qi1 = __ldg(qi + 16), qi2 = __ldg(qi + 32);

    float4 f0, f1, f2, d;
    f0.x = m00 * qj0.x + m01 * qj1.x + m02 * qj2.x;
    f0.y = m00 * qj0.y + m01 * qj1.y + m02 * qj2.y;
    f0.z = m00 * qj0.z + m01 * qj1.z + m02 * qj2.z;
    f0.w = m00 * qj0.w + m01 * qj1.w + m02 * qj2.w;
    f1.x = m10 * qj0.x + m11 * qj1.x + m12 * qj2.x;
    f1.y = m10 * qj0.y + m11 * qj1.y + m12 * qj2.y;
    f1.z = m10 * qj0.z + m11 * qj1.z + m12 * qj2.z;
    f1.w = m10 * qj0.w + m11 * qj1.w + m12 * qj2.w;
    f2.x = m20 * qj0.x + m21 * qj1.x + m22 * qj2.x;
    f2.y = m20 * qj0.y + m21 * qj1.y + m22 * qj2.y;
    f2.z = m20 * qj0.z + m21 * qj1.z + m22 * qj2.z;
    f2.w = m20 * qj0.w + m21 * qj1.w + m22 * qj2.w;

    d.x = qi0.x * f0.x + qi1.x * f1.x + qi2.x * f2.x;
    d.y = qi0.y * f0.y + qi1.y * f1.y + qi2.y * f2.y;
    d.z = qi0.z * f0.z + qi1.z * f1.z + qi2.z * f2.z;
    d.w = qi0.w * f0.w + qi1.w * f1.w + qi2.w * f2.w;

    float* dst = out + (size_t)r * 64 + 4 * l;
    asm volatile("red.global.add.v4.f32 [%0], {%1, %2, %3, %4};"
                 :: "l"(dst), "f"(d.x), "f"(d.y), "f"(d.z), "f"(d.w)
                 : "memory");
}

// ---------------------------------------------------------------------------
extern "C" void kernel_launch(void* const* d_in, const int* in_sizes, int n_in,
                              void* d_out, int out_size)
{
    const float* x         = (const float*)d_in[0];
    const float* vec       = (const float*)d_in[1];
    const int*   senders   = (const int*)  d_in[2];
    const int*   receivers = (const int*)  d_in[3];
    const float* im        = (const float*)d_in[4];
    const float* ln_scale  = (const float*)d_in[5];
    const float* ln_bias   = (const float*)d_in[6];
    const float* vln       = (const float*)d_in[7];
    const float* w1        = (const float*)d_in[8];
    const float* b1        = (const float*)d_in[9];
    const float* w2        = (const float*)d_in[10];
    const float* b2        = (const float*)d_in[11];

    int N = in_sizes[0] / CCH;
    int E = in_sizes[2];

    cudaMemsetAsync(d_out, 0, (size_t)out_size * sizeof(float));

    const int smem = (64 * 128 + 128 * 64 + K1_WARPS * 64 * 4 + K1_WARPS * 4 * 128)
                     * (int)sizeof(float);                       // 112 KB
    static bool attr_set = false;
    if (!attr_set) {
        cudaFuncSetAttribute(k_node, cudaFuncAttributeMaxDynamicSharedMemorySize, smem);
        attr_set = true;
    }
    int nodes_per_block = K1_WARPS * 4;
    k_node<<<(N + nodes_per_block - 1) / nodes_per_block, 32 * K1_WARPS, smem>>>(
        x, vec, ln_scale, ln_bias, vln, w1, b1, w2, b2, N);

    long long tot = (long long)E * 16;
    int eblocks = (int)((tot + 255) / 256);
    k_edge<<<eblocks, 256>>>(senders, receivers, im, (float*)d_out, E);
}

// round 10
// speedup vs baseline: 2.0742x; 1.0335x over previous
#include <cuda_runtime.h>
#include <cuda_bf16.h>

// PoleInteraction, q-fused form:
//   p = MLP(LayerNorm(x));  q[n,i,c] = vln[c]*p[n,c]*vec[n,i,c]
//   dEnergy[e,c] = sum_ij q[r,i,c]*M[e,i,j]*q[s,j,c]
//   dx = segment_sum(dEnergy, receivers)   (red.global.add.v4)

#define NODES_MAX 50000
#define CCH 64
#define K1_WARPS 16   // 512-thread blocks: weights amortized over 2x warps

__device__ float g_q[NODES_MAX * 3 * CCH];  // fused w*p*vec field [N,3,64]

// ---------------------------------------------------------------------------
// K1: LayerNorm + MLP (64 -> 128 silu -> 64) + q epilogue + out-row zeroing.
// Warp per 4 nodes; 16 warps/block share one smem copy of the weights.
// ---------------------------------------------------------------------------
__global__ __launch_bounds__(32 * K1_WARPS) void k_node(
    const float* __restrict__ x,
    const float* __restrict__ vec,
    const float* __restrict__ ln_s, const float* __restrict__ ln_b,
    const float* __restrict__ vw,
    const float* __restrict__ w1, const float* __restrict__ b1,
    const float* __restrict__ w2, const float* __restrict__ b2,
    float* __restrict__ out,
    int N)
{
    extern __shared__ float sm[];
    float* w1s = sm;                         // 64*128
    float* w2s = w1s + 64 * 128;             // 128*64
    float* xts = w2s + 128 * 64;             // K1_WARPS * 64 ch * 4 nodes (transposed)
    float* hs  = xts + K1_WARPS * 64 * 4;    // K1_WARPS * 4 nodes * 128

    int tid = threadIdx.x;
    for (int i = tid; i < (64 * 128) / 4; i += blockDim.x)
        reinterpret_cast<float4*>(w1s)[i] = reinterpret_cast<const float4*>(w1)[i];
    for (int i = tid; i < (128 * 64) / 4; i += blockDim.x)
        reinterpret_cast<float4*>(w2s)[i] = reinterpret_cast<const float4*>(w2)[i];
    __syncthreads();

    int warp = tid >> 5, lane = tid & 31;
    int node0 = (blockIdx.x * K1_WARPS + warp) * 4;
    if (node0 >= N) return;
    float* xt = xts + warp * 64 * 4;     // xt[c*4 + u]
    float* hh = hs  + warp * 4 * 128;    // hh[u*128 + k]

    // zero this warp's output rows (replaces the global memset; k_edge runs after)
    {
        int nvalid = min(4, N - node0);
        float4 z = make_float4(0.f, 0.f, 0.f, 0.f);
        float4* orow = reinterpret_cast<float4*>(out + (size_t)node0 * 64);
        for (int i = lane; i < nvalid * 16; i += 32) orow[i] = z;
    }

    float2 lns = reinterpret_cast<const float2*>(ln_s)[lane];
    float2 lnb = reinterpret_cast<const float2*>(ln_b)[lane];

    // LayerNorm for 4 nodes; thread owns channels 2*lane, 2*lane+1.
    #pragma unroll
    for (int u = 0; u < 4; u++) {
        int n = node0 + u;
        float2 v = make_float2(0.f, 0.f);
        if (n < N) v = reinterpret_cast<const float2*>(x + (size_t)n * 64)[lane];
        float s  = v.x + v.y;
        float sq = v.x * v.x + v.y * v.y;
        #pragma unroll
        for (int o = 16; o; o >>= 1) {
            s  += __shfl_xor_sync(0xffffffffu, s,  o);
            sq += __shfl_xor_sync(0xffffffffu, sq, o);
        }
        float mean = s * (1.f / 64.f);
        float var  = sq * (1.f / 64.f) - mean * mean;
        float rstd = rsqrtf(var + 1e-5f);
        xt[(2 * lane    ) * 4 + u] = (v.x - mean) * rstd * lns.x + lnb.x;
        xt[(2 * lane + 1) * 4 + u] = (v.y - mean) * rstd * lns.y + lnb.y;
    }
    __syncwarp();

    // Layer 1: thread computes h[4*lane..4*lane+3] for 4 nodes.
    float4 bb1 = reinterpret_cast<const float4*>(b1)[lane];
    float4 acc0 = bb1, acc1 = bb1, acc2 = bb1, acc3 = bb1;
    #pragma unroll 4
    for (int c = 0; c < 64; c++) {
        float4 xv = reinterpret_cast<float4*>(xt)[c];           // nodes 0..3 @ channel c
        float4 w  = reinterpret_cast<float4*>(w1s + c * 128)[lane];
        acc0.x += xv.x * w.x; acc0.y += xv.x * w.y; acc0.z += xv.x * w.z; acc0.w += xv.x * w.w;
        acc1.x += xv.y * w.x; acc1.y += xv.y * w.y; acc1.z += xv.y * w.z; acc1.w += xv.y * w.w;
        acc2.x += xv.z * w.x; acc2.y += xv.z * w.y; acc2.z += xv.z * w.z; acc2.w += xv.z * w.w;
        acc3.x += xv.w * w.x; acc3.y += xv.w * w.y; acc3.z += xv.w * w.z; acc3.w += xv.w * w.w;
    }

    // silu + stage h
    {
        float4 a[4] = {acc0, acc1, acc2, acc3};
        #pragma unroll
        for (int u = 0; u < 4; u++) {
            float4 v = a[u];
            v.x = v.x / (1.f + __expf(-v.x));
            v.y = v.y / (1.f + __expf(-v.y));
            v.z = v.z / (1.f + __expf(-v.z));
            v.w = v.w / (1.f + __expf(-v.w));
            reinterpret_cast<float4*>(hh + u * 128)[lane] = v;
        }
    }
    __syncwarp();

    // Layer 2: thread computes p[2*lane], p[2*lane+1] for 4 nodes.
    float2 bb2 = reinterpret_cast<const float2*>(b2)[lane];
    float2 p0 = bb2, p1 = bb2, p2 = bb2, p3 = bb2;
    #pragma unroll 2
    for (int k4 = 0; k4 < 32; k4++) {
        float4 h0 = reinterpret_cast<float4*>(hh + 0 * 128)[k4];
        float4 h1 = reinterpret_cast<float4*>(hh + 1 * 128)[k4];
        float4 h2 = reinterpret_cast<float4*>(hh + 2 * 128)[k4];
        float4 h3 = reinterpret_cast<float4*>(hh + 3 * 128)[k4];
        #pragma unroll
        for (int j = 0; j < 4; j++) {
            float2 w = reinterpret_cast<float2*>(w2s + (4 * k4 + j) * 64)[lane];
            float a0 = (j == 0) ? h0.x : (j == 1) ? h0.y : (j == 2) ? h0.z : h0.w;
            float a1 = (j == 0) ? h1.x : (j == 1) ? h1.y : (j == 2) ? h1.z : h1.w;
            float a2 = (j == 0) ? h2.x : (j == 1) ? h2.y : (j == 2) ? h2.z : h2.w;
            float a3 = (j == 0) ? h3.x : (j == 1) ? h3.y : (j == 2) ? h3.z : h3.w;
            p0.x += a0 * w.x; p0.y += a0 * w.y;
            p1.x += a1 * w.x; p1.y += a1 * w.y;
            p2.x += a2 * w.x; p2.y += a2 * w.y;
            p3.x += a3 * w.x; p3.y += a3 * w.y;
        }
    }

    // Epilogue: q[n,i,c] = vln[c] * p[n,c] * vec[n,i,c]
    float2 wv = reinterpret_cast<const float2*>(vw)[lane];
    {
        float2 p[4] = {p0, p1, p2, p3};
        #pragma unroll
        for (int u = 0; u < 4; u++) {
            int n = node0 + u;
            if (n >= N) continue;
            float2 pw;
            pw.x = p[u].x * wv.x;
            pw.y = p[u].y * wv.y;
            const float2* vsrc = reinterpret_cast<const float2*>(vec + (size_t)n * 192);
            float2*       qdst = reinterpret_cast<float2*>(g_q + (size_t)n * 192);
            #pragma unroll
            for (int i = 0; i < 3; i++) {
                float2 v = vsrc[i * 32 + lane];
                float2 qq;
                qq.x = pw.x * v.x;
                qq.y = pw.y * v.y;
                qdst[i * 32 + lane] = qq;
            }
        }
    }
}

// ---------------------------------------------------------------------------
// K2: per-edge phase, ILP-2: 16 lanes per group, 2 edges per group.
// Both edges' gathers issue before either compute -> 2x outstanding loads
// per warp, pushing L1tex toward saturation.
// ---------------------------------------------------------------------------
__device__ __forceinline__ float4 pole_energy(
    float mv,
    float4 qj0, float4 qj1, float4 qj2,
    float4 qi0, float4 qi1, float4 qi2)
{
    float m00 = __shfl_sync(0xffffffffu, mv, 0, 16);
    float m01 = __shfl_sync(0xffffffffu, mv, 1, 16);
    float m02 = __shfl_sync(0xffffffffu, mv, 2, 16);
    float m10 = __shfl_sync(0xffffffffu, mv, 3, 16);
    float m11 = __shfl_sync(0xffffffffu, mv, 4, 16);
    float m12 = __shfl_sync(0xffffffffu, mv, 5, 16);
    float m20 = __shfl_sync(0xffffffffu, mv, 6, 16);
    float m21 = __shfl_sync(0xffffffffu, mv, 7, 16);
    float m22 = __shfl_sync(0xffffffffu, mv, 8, 16);

    float4 f0, f1, f2, d;
    f0.x = m00 * qj0.x + m01 * qj1.x + m02 * qj2.x;
    f0.y = m00 * qj0.y + m01 * qj1.y + m02 * qj2.y;
    f0.z = m00 * qj0.z + m01 * qj1.z + m02 * qj2.z;
    f0.w = m00 * qj0.w + m01 * qj1.w + m02 * qj2.w;
    f1.x = m10 * qj0.x + m11 * qj1.x + m12 * qj2.x;
    f1.y = m10 * qj0.y + m11 * qj1.y + m12 * qj2.y;
    f1.z = m10 * qj0.z + m11 * qj1.z + m12 * qj2.z;
    f1.w = m10 * qj0.w + m11 * qj1.w + m12 * qj2.w;
    f2.x = m20 * qj0.x + m21 * qj1.x + m22 * qj2.x;
    f2.y = m20 * qj0.y + m21 * qj1.y + m22 * qj2.y;
    f2.z = m20 * qj0.z + m21 * qj1.z + m22 * qj2.z;
    f2.w = m20 * qj0.w + m21 * qj1.w + m22 * qj2.w;

    d.x = qi0.x * f0.x + qi1.x * f1.x + qi2.x * f2.x;
    d.y = qi0.y * f0.y + qi1.y * f1.y + qi2.y * f2.y;
    d.z = qi0.z * f0.z + qi1.z * f1.z + qi2.z * f2.z;
    d.w = qi0.w * f0.w + qi1.w * f1.w + qi2.w * f2.w;
    return d;
}

__global__ __launch_bounds__(256) void k_edge(
    const int*   __restrict__ senders,
    const int*   __restrict__ receivers,
    const float* __restrict__ Mm,
    float* __restrict__ out,
    int E)
{
    int t = blockIdx.x * blockDim.x + threadIdx.x;
    int g = t >> 4;
    int l = t & 15;
    int eA = g * 2;
    if (eA >= E) return;
    bool hasB = (eA + 1) < E;
    int eB = hasB ? eA + 1 : eA;     // clamp: loads valid, result discarded

    // --- issue all gathers for both edges ---
    int sA = __ldg(senders + eA), rA = __ldg(receivers + eA);
    int sB = __ldg(senders + eB), rB = __ldg(receivers + eB);

    float mvA = 0.f, mvB = 0.f;
    if (l < 9) {
        mvA = __ldg(Mm + (size_t)eA * 9 + l);
        mvB = __ldg(Mm + (size_t)eB * 9 + l);
    }

    const float4* qjA = reinterpret_cast<const float4*>(g_q + (size_t)sA * 192) + l;
    const float4* qiA = reinterpret_cast<const float4*>(g_q + (size_t)rA * 192) + l;
    const float4* qjB = reinterpret_cast<const float4*>(g_q + (size_t)sB * 192) + l;
    const float4* qiB = reinterpret_cast<const float4*>(g_q + (size_t)rB * 192) + l;

    float4 qjA0 = __ldg(qjA + 0), qjA1 = __ldg(qjA + 16), qjA2 = __ldg(qjA + 32);
    float4 qiA0 = __ldg(qiA + 0), qiA1 = __ldg(qiA + 16), qiA2 = __ldg(qiA + 32);
    float4 qjB0 = __ldg(qjB + 0), qjB1 = __ldg(qjB + 16), qjB2 = __ldg(qjB + 32);
    float4 qiB0 = __ldg(qiB + 0), qiB1 = __ldg(qiB + 16), qiB2 = __ldg(qiB + 32);

    // --- compute + scatter edge A ---
    float4 dA = pole_energy(mvA, qjA0, qjA1, qjA2, qiA0, qiA1, qiA2);
    {
        float* dst = out + (size_t)rA * 64 + 4 * l;
        asm volatile("red.global.add.v4.f32 [%0], {%1, %2, %3, %4};"
                     :: "l"(dst), "f"(dA.x), "f"(dA.y), "f"(dA.z), "f"(dA.w)
                     : "memory");
    }

    // --- compute + scatter edge B ---
    if (hasB) {
        float4 dB = pole_energy(mvB, qjB0, qjB1, qjB2, qiB0, qiB1, qiB2);
        float* dst = out + (size_t)rB * 64 + 4 * l;
        asm volatile("red.global.add.v4.f32 [%0], {%1, %2, %3, %4};"
                     :: "l"(dst), "f"(dB.x), "f"(dB.y), "f"(dB.z), "f"(dB.w)
                     : "memory");
    }
}

// ---------------------------------------------------------------------------
extern "C" void kernel_launch(void* const* d_in, const int* in_sizes, int n_in,
                              void* d_out, int out_size)
{
    const float* x         = (const float*)d_in[0];
    const float* vec       = (const float*)d_in[1];
    const int*   senders   = (const int*)  d_in[2];
    const int*   receivers = (const int*)  d_in[3];
    const float* im        = (const float*)d_in[4];
    const float* ln_scale  = (const float*)d_in[5];
    const float* ln_bias   = (const float*)d_in[6];
    const float* vln       = (const float*)d_in[7];
    const float* w1        = (const float*)d_in[8];
    const float* b1        = (const float*)d_in[9];
    const float* w2        = (const float*)d_in[10];
    const float* b2        = (const float*)d_in[11];

    int N = in_sizes[0] / CCH;
    int E = in_sizes[2];

    const int smem = (64 * 128 + 128 * 64 + K1_WARPS * 64 * 4 + K1_WARPS * 4 * 128)
                     * (int)sizeof(float);                       // 112 KB
    static bool attr_set = false;
    if (!attr_set) {
        cudaFuncSetAttribute(k_node, cudaFuncAttributeMaxDynamicSharedMemorySize, smem);
        attr_set = true;
    }
    int nodes_per_block = K1_WARPS * 4;
    k_node<<<(N + nodes_per_block - 1) / nodes_per_block, 32 * K1_WARPS, smem>>>(
        x, vec, ln_scale, ln_bias, vln, w1, b1, w2, b2, (float*)d_out, N);

    int ngroups = (E + 1) / 2;                    // 2 edges per 16-lane group
    long long tot = (long long)ngroups * 16;
    int eblocks = (int)((tot + 255) / 256);
    k_edge<<<eblocks, 256>>>(senders, receivers, im, (float*)d_out, E);
}

// round 11
// speedup vs baseline: 2.0994x; 1.0121x over previous
#include <cuda_runtime.h>
#include <cuda_bf16.h>
#include <cstdint>

// PoleInteraction, q-fused form:
//   p = MLP(LayerNorm(x));  q[n,i,c] = vln[c]*p[n,c]*vec[n,i,c]
//   dEnergy[e,c] = sum_ij q[r,i,c]*M[e,i,j]*q[s,j,c]
//   dx = segment_sum(dEnergy, receivers)   (red.global.add.v4)
// MLP inner loops use packed fma.rn.f32x2 (FFMA2): 2x fp32 FMA throughput,
// bit-exact fp32 results.

#define NODES_MAX 50000
#define CCH 64
#define K1_WARPS 16   // 512-thread blocks: weights amortized over 2x warps

__device__ float g_q[NODES_MAX * 3 * CCH];  // fused w*p*vec field [N,3,64]

// packed f32x2 helpers
#define PACKF2(d, lo, hi) \
    asm("mov.b64 %0, {%1, %2};" : "=l"(d) : "r"(__float_as_uint(lo)), "r"(__float_as_uint(hi)))
#define UNPACKF2(lo, hi, s) do { \
    unsigned _a, _b; \
    asm("mov.b64 {%0, %1}, %2;" : "=r"(_a), "=r"(_b) : "l"(s)); \
    lo = __uint_as_float(_a); hi = __uint_as_float(_b); } while (0)
#define FMAF2(d, a, b, c) \
    asm("fma.rn.f32x2 %0, %1, %2, %3;" : "=l"(d) : "l"(a), "l"(b), "l"(c))

// ---------------------------------------------------------------------------
// K1: LayerNorm + MLP (64 -> 128 silu -> 64) + q epilogue + out-row zeroing.
// Warp per 4 nodes; 16 warps/block share one smem copy of the weights.
// ---------------------------------------------------------------------------
__global__ __launch_bounds__(32 * K1_WARPS) void k_node(
    const float* __restrict__ x,
    const float* __restrict__ vec,
    const float* __restrict__ ln_s, const float* __restrict__ ln_b,
    const float* __restrict__ vw,
    const float* __restrict__ w1, const float* __restrict__ b1,
    const float* __restrict__ w2, const float* __restrict__ b2,
    float* __restrict__ out,
    int N)
{
    extern __shared__ float sm[];
    float* w1s = sm;                         // 64*128
    float* w2s = w1s + 64 * 128;             // 128*64
    float* xts = w2s + 128 * 64;             // K1_WARPS * 64 ch * 4 nodes (transposed)
    float* hs  = xts + K1_WARPS * 64 * 4;    // K1_WARPS * 4 nodes * 128

    int tid = threadIdx.x;
    for (int i = tid; i < (64 * 128) / 4; i += blockDim.x)
        reinterpret_cast<float4*>(w1s)[i] = reinterpret_cast<const float4*>(w1)[i];
    for (int i = tid; i < (128 * 64) / 4; i += blockDim.x)
        reinterpret_cast<float4*>(w2s)[i] = reinterpret_cast<const float4*>(w2)[i];
    __syncthreads();

    int warp = tid >> 5, lane = tid & 31;
    int node0 = (blockIdx.x * K1_WARPS + warp) * 4;
    if (node0 >= N) return;
    float* xt = xts + warp * 64 * 4;     // xt[c*4 + u]
    float* hh = hs  + warp * 4 * 128;    // hh[u*128 + k]

    // zero this warp's output rows (replaces the global memset; k_edge runs after)
    {
        int nvalid = min(4, N - node0);
        float4 z = make_float4(0.f, 0.f, 0.f, 0.f);
        float4* orow = reinterpret_cast<float4*>(out + (size_t)node0 * 64);
        for (int i = lane; i < nvalid * 16; i += 32) orow[i] = z;
    }

    float2 lns = reinterpret_cast<const float2*>(ln_s)[lane];
    float2 lnb = reinterpret_cast<const float2*>(ln_b)[lane];

    // LayerNorm for 4 nodes; thread owns channels 2*lane, 2*lane+1.
    #pragma unroll
    for (int u = 0; u < 4; u++) {
        int n = node0 + u;
        float2 v = make_float2(0.f, 0.f);
        if (n < N) v = reinterpret_cast<const float2*>(x + (size_t)n * 64)[lane];
        float s  = v.x + v.y;
        float sq = v.x * v.x + v.y * v.y;
        #pragma unroll
        for (int o = 16; o; o >>= 1) {
            s  += __shfl_xor_sync(0xffffffffu, s,  o);
            sq += __shfl_xor_sync(0xffffffffu, sq, o);
        }
        float mean = s * (1.f / 64.f);
        float var  = sq * (1.f / 64.f) - mean * mean;
        float rstd = rsqrtf(var + 1e-5f);
        xt[(2 * lane    ) * 4 + u] = (v.x - mean) * rstd * lns.x + lnb.x;
        xt[(2 * lane + 1) * 4 + u] = (v.y - mean) * rstd * lns.y + lnb.y;
    }
    __syncwarp();

    // Layer 1 (packed): acc[u][h] = h-outputs (4*lane+2h, 4*lane+2h+1) of node u.
    // Weights read as LDS64 pairs (natural packing); x broadcast packed per node.
    float4 bb1 = reinterpret_cast<const float4*>(b1)[lane];
    uint64_t b1lo, b1hi;
    PACKF2(b1lo, bb1.x, bb1.y);
    PACKF2(b1hi, bb1.z, bb1.w);
    uint64_t acc[4][2];
    #pragma unroll
    for (int u = 0; u < 4; u++) { acc[u][0] = b1lo; acc[u][1] = b1hi; }

    #pragma unroll 4
    for (int c = 0; c < 64; c++) {
        float4 xv = reinterpret_cast<float4*>(xt)[c];            // nodes 0..3 @ channel c
        const uint64_t* wrow = reinterpret_cast<const uint64_t*>(w1s + c * 128);
        uint64_t wlo = wrow[2 * lane], whi = wrow[2 * lane + 1]; // (w[4l],w[4l+1]),(w[4l+2],w[4l+3])
        uint64_t xx;
        PACKF2(xx, xv.x, xv.x);
        FMAF2(acc[0][0], xx, wlo, acc[0][0]); FMAF2(acc[0][1], xx, whi, acc[0][1]);
        PACKF2(xx, xv.y, xv.y);
        FMAF2(acc[1][0], xx, wlo, acc[1][0]); FMAF2(acc[1][1], xx, whi, acc[1][1]);
        PACKF2(xx, xv.z, xv.z);
        FMAF2(acc[2][0], xx, wlo, acc[2][0]); FMAF2(acc[2][1], xx, whi, acc[2][1]);
        PACKF2(xx, xv.w, xv.w);
        FMAF2(acc[3][0], xx, wlo, acc[3][0]); FMAF2(acc[3][1], xx, whi, acc[3][1]);
    }

    // silu + stage h
    #pragma unroll
    for (int u = 0; u < 4; u++) {
        float4 v;
        UNPACKF2(v.x, v.y, acc[u][0]);
        UNPACKF2(v.z, v.w, acc[u][1]);
        v.x = v.x / (1.f + __expf(-v.x));
        v.y = v.y / (1.f + __expf(-v.y));
        v.z = v.z / (1.f + __expf(-v.z));
        v.w = v.w / (1.f + __expf(-v.w));
        reinterpret_cast<float4*>(hh + u * 128)[lane] = v;
    }
    __syncwarp();

    // Layer 2 (packed): p[u] = packed channels (2*lane, 2*lane+1) of node u.
    // w2 rows read as LDS64 pairs; h broadcast packed per node.
    float2 bb2 = reinterpret_cast<const float2*>(b2)[lane];
    uint64_t pb;
    PACKF2(pb, bb2.x, bb2.y);
    uint64_t p[4] = {pb, pb, pb, pb};

    #pragma unroll 2
    for (int k4 = 0; k4 < 32; k4++) {
        float4 h0 = reinterpret_cast<float4*>(hh + 0 * 128)[k4];
        float4 h1 = reinterpret_cast<float4*>(hh + 1 * 128)[k4];
        float4 h2 = reinterpret_cast<float4*>(hh + 2 * 128)[k4];
        float4 h3 = reinterpret_cast<float4*>(hh + 3 * 128)[k4];
        #pragma unroll
        for (int j = 0; j < 4; j++) {
            uint64_t w = reinterpret_cast<const uint64_t*>(w2s + (4 * k4 + j) * 64)[lane];
            float a0 = (j == 0) ? h0.x : (j == 1) ? h0.y : (j == 2) ? h0.z : h0.w;
            float a1 = (j == 0) ? h1.x : (j == 1) ? h1.y : (j == 2) ? h1.z : h1.w;
            float a2 = (j == 0) ? h2.x : (j == 1) ? h2.y : (j == 2) ? h2.z : h2.w;
            float a3 = (j == 0) ? h3.x : (j == 1) ? h3.y : (j == 2) ? h3.z : h3.w;
            uint64_t hb;
            PACKF2(hb, a0, a0); FMAF2(p[0], hb, w, p[0]);
            PACKF2(hb, a1, a1); FMAF2(p[1], hb, w, p[1]);
            PACKF2(hb, a2, a2); FMAF2(p[2], hb, w, p[2]);
            PACKF2(hb, a3, a3); FMAF2(p[3], hb, w, p[3]);
        }
    }

    // Epilogue: q[n,i,c] = vln[c] * p[n,c] * vec[n,i,c]
    float2 wv = reinterpret_cast<const float2*>(vw)[lane];
    #pragma unroll
    for (int u = 0; u < 4; u++) {
        int n = node0 + u;
        if (n >= N) continue;
        float px, py;
        UNPACKF2(px, py, p[u]);
        float2 pw;
        pw.x = px * wv.x;
        pw.y = py * wv.y;
        const float2* vsrc = reinterpret_cast<const float2*>(vec + (size_t)n * 192);
        float2*       qdst = reinterpret_cast<float2*>(g_q + (size_t)n * 192);
        #pragma unroll
        for (int i = 0; i < 3; i++) {
            float2 v = vsrc[i * 32 + lane];
            float2 qq;
            qq.x = pw.x * v.x;
            qq.y = pw.y * v.y;
            qdst[i * 32 + lane] = qq;
        }
    }
}

// ---------------------------------------------------------------------------
// K2: per-edge phase, ILP-2: 16 lanes per group, 2 edges per group.
// ---------------------------------------------------------------------------
__device__ __forceinline__ float4 pole_energy(
    float mv,
    float4 qj0, float4 qj1, float4 qj2,
    float4 qi0, float4 qi1, float4 qi2)
{
    float m00 = __shfl_sync(0xffffffffu, mv, 0, 16);
    float m01 = __shfl_sync(0xffffffffu, mv, 1, 16);
    float m02 = __shfl_sync(0xffffffffu, mv, 2, 16);
    float m10 = __shfl_sync(0xffffffffu, mv, 3, 16);
    float m11 = __shfl_sync(0xffffffffu, mv, 4, 16);
    float m12 = __shfl_sync(0xffffffffu, mv, 5, 16);
    float m20 = __shfl_sync(0xffffffffu, mv, 6, 16);
    float m21 = __shfl_sync(0xffffffffu, mv, 7, 16);
    float m22 = __shfl_sync(0xffffffffu, mv, 8, 16);

    float4 f0, f1, f2, d;
    f0.x = m00 * qj0.x + m01 * qj1.x + m02 * qj2.x;
    f0.y = m00 * qj0.y + m01 * qj1.y + m02 * qj2.y;
    f0.z = m00 * qj0.z + m01 * qj1.z + m02 * qj2.z;
    f0.w = m00 * qj0.w + m01 * qj1.w + m02 * qj2.w;
    f1.x = m10 * qj0.x + m11 * qj1.x + m12 * qj2.x;
    f1.y = m10 * qj0.y + m11 * qj1.y + m12 * qj2.y;
    f1.z = m10 * qj0.z + m11 * qj1.z + m12 * qj2.z;
    f1.w = m10 * qj0.w + m11 * qj1.w + m12 * qj2.w;
    f2.x = m20 * qj0.x + m21 * qj1.x + m22 * qj2.x;
    f2.y = m20 * qj0.y + m21 * qj1.y + m22 * qj2.y;
    f2.z = m20 * qj0.z + m21 * qj1.z + m22 * qj2.z;
    f2.w = m20 * qj0.w + m21 * qj1.w + m22 * qj2.w;

    d.x = qi0.x * f0.x + qi1.x * f1.x + qi2.x * f2.x;
    d.y = qi0.y * f0.y + qi1.y * f1.y + qi2.y * f2.y;
    d.z = qi0.z * f0.z + qi1.z * f1.z + qi2.z * f2.z;
    d.w = qi0.w * f0.w + qi1.w * f1.w + qi2.w * f2.w;
    return d;
}

__global__ __launch_bounds__(256) void k_edge(
    const int*   __restrict__ senders,
    const int*   __restrict__ receivers,
    const float* __restrict__ Mm,
    float* __restrict__ out,
    int E)
{
    int t = blockIdx.x * blockDim.x + threadIdx.x;
    int g = t >> 4;
    int l = t & 15;
    int eA = g * 2;
    if (eA >= E) return;
    bool hasB = (eA + 1) < E;
    int eB = hasB ? eA + 1 : eA;

    int sA = __ldg(senders + eA), rA = __ldg(receivers + eA);
    int sB = __ldg(senders + eB), rB = __ldg(receivers + eB);

    float mvA = 0.f, mvB = 0.f;
    if (l < 9) {
        mvA = __ldg(Mm + (size_t)eA * 9 + l);
        mvB = __ldg(Mm + (size_t)eB * 9 + l);
    }

    const float4* qjA = reinterpret_cast<const float4*>(g_q + (size_t)sA * 192) + l;
    const float4* qiA = reinterpret_cast<const float4*>(g_q + (size_t)rA * 192) + l;
    const float4* qjB = reinterpret_cast<const float4*>(g_q + (size_t)sB * 192) + l;
    const float4* qiB = reinterpret_cast<const float4*>(g_q + (size_t)rB * 192) + l;

    float4 qjA0 = __ldg(qjA + 0), qjA1 = __ldg(qjA + 16), qjA2 = __ldg(qjA + 32);
    float4 qiA0 = __ldg(qiA + 0), qiA1 = __ldg(qiA + 16), qiA2 = __ldg(qiA + 32);
    float4 qjB0 = __ldg(qjB + 0), qjB1 = __ldg(qjB + 16), qjB2 = __ldg(qjB + 32);
    float4 qiB0 = __ldg(qiB + 0), qiB1 = __ldg(qiB + 16), qiB2 = __ldg(qiB + 32);

    float4 dA = pole_energy(mvA, qjA0, qjA1, qjA2, qiA0, qiA1, qiA2);
    {
        float* dst = out + (size_t)rA * 64 + 4 * l;
        asm volatile("red.global.add.v4.f32 [%0], {%1, %2, %3, %4};"
                     :: "l"(dst), "f"(dA.x), "f"(dA.y), "f"(dA.z), "f"(dA.w)
                     : "memory");
    }

    if (hasB) {
        float4 dB = pole_energy(mvB, qjB0, qjB1, qjB2, qiB0, qiB1, qiB2);
        float* dst = out + (size_t)rB * 64 + 4 * l;
        asm volatile("red.global.add.v4.f32 [%0], {%1, %2, %3, %4};"
                     :: "l"(dst), "f"(dB.x), "f"(dB.y), "f"(dB.z), "f"(dB.w)
                     : "memory");
    }
}

// ---------------------------------------------------------------------------
extern "C" void kernel_launch(void* const* d_in, const int* in_sizes, int n_in,
                              void* d_out, int out_size)
{
    const float* x         = (const float*)d_in[0];
    const float* vec       = (const float*)d_in[1];
    const int*   senders   = (const int*)  d_in[2];
    const int*   receivers = (const int*)  d_in[3];
    const float* im        = (const float*)d_in[4];
    const float* ln_scale  = (const float*)d_in[5];
    const float* ln_bias   = (const float*)d_in[6];
    const float* vln       = (const float*)d_in[7];
    const float* w1        = (const float*)d_in[8];
    const float* b1        = (const float*)d_in[9];
    const float* w2        = (const float*)d_in[10];
    const float* b2        = (const float*)d_in[11];

    int N = in_sizes[0] / CCH;
    int E = in_sizes[2];

    const int smem = (64 * 128 + 128 * 64 + K1_WARPS * 64 * 4 + K1_WARPS * 4 * 128)
                     * (int)sizeof(float);                       // 112 KB
    static bool attr_set = false;
    if (!attr_set) {
        cudaFuncSetAttribute(k_node, cudaFuncAttributeMaxDynamicSharedMemorySize, smem);
        attr_set = true;
    }
    int nodes_per_block = K1_WARPS * 4;
    k_node<<<(N + nodes_per_block - 1) / nodes_per_block, 32 * K1_WARPS, smem>>>(
        x, vec, ln_scale, ln_bias, vln, w1, b1, w2, b2, (float*)d_out, N);

    int ngroups = (E + 1) / 2;                    // 2 edges per 16-lane group
    long long tot = (long long)ngroups * 16;
    int eblocks = (int)((tot + 255) / 256);
    k_edge<<<eblocks, 256>>>(senders, receivers, im, (float*)d_out, E);
}

// round 13
// speedup vs baseline: 2.1271x; 1.0132x over previous
#include <cuda_runtime.h>
#include <cuda_bf16.h>
#include <cstdint>

// PoleInteraction, q-fused form:
//   p = MLP(LayerNorm(x));  q[n,i,c] = vln[c]*p[n,c]*vec[n,i,c]
//   dEnergy[e,c] = sum_ij q[r,i,c]*M[e,i,j]*q[s,j,c]
//   dx = segment_sum(dEnergy, receivers)   (red.global.add.v4)
// k_node: 8 nodes/warp -> weight-LDS amortized 2x; packed fma.rn.f32x2.

#define NODES_MAX 50000
#define CCH 64
#define K1_WARPS 8    // 256-thread blocks
#define NPW 8         // nodes per warp

__device__ float g_q[NODES_MAX * 3 * CCH];  // fused w*p*vec field [N,3,64]

// packed f32x2 helpers
#define PACKF2(d, lo, hi) \
    asm("mov.b64 %0, {%1, %2};" : "=l"(d) : "r"(__float_as_uint(lo)), "r"(__float_as_uint(hi)))
#define UNPACKF2(lo, hi, s) do { \
    unsigned _a, _b; \
    asm("mov.b64 {%0, %1}, %2;" : "=r"(_a), "=r"(_b) : "l"(s)); \
    lo = __uint_as_float(_a); hi = __uint_as_float(_b); } while (0)
#define FMAF2(d, a, b, c) \
    asm("fma.rn.f32x2 %0, %1, %2, %3;" : "=l"(d) : "l"(a), "l"(b), "l"(c))

// ---------------------------------------------------------------------------
// K1: LayerNorm + MLP (64 -> 128 silu -> 64) + q epilogue + out-row zeroing.
// Warp per 8 nodes; 8 warps/block share one smem copy of the weights (112KB,
// 2 blocks/SM -> 16 warps/SM with 2x per-warp ILP).
// ---------------------------------------------------------------------------
__global__ __launch_bounds__(32 * K1_WARPS) void k_node(
    const float* __restrict__ x,
    const float* __restrict__ vec,
    const float* __restrict__ ln_s, const float* __restrict__ ln_b,
    const float* __restrict__ vw,
    const float* __restrict__ w1, const float* __restrict__ b1,
    const float* __restrict__ w2, const float* __restrict__ b2,
    float* __restrict__ out,
    int N)
{
    extern __shared__ float sm[];
    float* w1s = sm;                          // 64*128
    float* w2s = w1s + 64 * 128;              // 128*64
    float* xts = w2s + 128 * 64;              // K1_WARPS * 64 ch * NPW (transposed)
    float* hs  = xts + K1_WARPS * 64 * NPW;   // K1_WARPS * NPW * 128

    int tid = threadIdx.x;
    for (int i = tid; i < (64 * 128) / 4; i += blockDim.x)
        reinterpret_cast<float4*>(w1s)[i] = reinterpret_cast<const float4*>(w1)[i];
    for (int i = tid; i < (128 * 64) / 4; i += blockDim.x)
        reinterpret_cast<float4*>(w2s)[i] = reinterpret_cast<const float4*>(w2)[i];
    __syncthreads();

    int warp = tid >> 5, lane = tid & 31;
    int node0 = (blockIdx.x * K1_WARPS + warp) * NPW;
    if (node0 >= N) return;
    float* xt = xts + warp * 64 * NPW;    // xt[c*NPW + u]
    float* hh = hs  + warp * NPW * 128;   // hh[u*128 + k]

    // zero this warp's output rows (replaces the global memset)
    {
        int nvalid = min(NPW, N - node0);
        float4 z = make_float4(0.f, 0.f, 0.f, 0.f);
        float4* orow = reinterpret_cast<float4*>(out + (size_t)node0 * 64);
        for (int i = lane; i < nvalid * 16; i += 32) orow[i] = z;
    }

    float2 lns = reinterpret_cast<const float2*>(ln_s)[lane];
    float2 lnb = reinterpret_cast<const float2*>(ln_b)[lane];

    // LayerNorm for NPW nodes; thread owns channels 2*lane, 2*lane+1.
    #pragma unroll
    for (int u = 0; u < NPW; u++) {
        int n = node0 + u;
        float2 v = make_float2(0.f, 0.f);
        if (n < N) v = reinterpret_cast<const float2*>(x + (size_t)n * 64)[lane];
        float s  = v.x + v.y;
        float sq = v.x * v.x + v.y * v.y;
        #pragma unroll
        for (int o = 16; o; o >>= 1) {
            s  += __shfl_xor_sync(0xffffffffu, s,  o);
            sq += __shfl_xor_sync(0xffffffffu, sq, o);
        }
        float mean = s * (1.f / 64.f);
        float var  = sq * (1.f / 64.f) - mean * mean;
        float rstd = rsqrtf(var + 1e-5f);
        xt[(2 * lane    ) * NPW + u] = (v.x - mean) * rstd * lns.x + lnb.x;
        xt[(2 * lane + 1) * NPW + u] = (v.y - mean) * rstd * lns.y + lnb.y;
    }
    __syncwarp();

    // Layer 1 (packed): acc[u][h] = h-outputs (4*lane+2h, 4*lane+2h+1) of node u.
    float4 bb1 = reinterpret_cast<const float4*>(b1)[lane];
    uint64_t b1lo, b1hi;
    PACKF2(b1lo, bb1.x, bb1.y);
    PACKF2(b1hi, bb1.z, bb1.w);
    uint64_t acc[NPW][2];
    #pragma unroll
    for (int u = 0; u < NPW; u++) { acc[u][0] = b1lo; acc[u][1] = b1hi; }

    #pragma unroll 2
    for (int c = 0; c < 64; c++) {
        float4 xa = reinterpret_cast<float4*>(xt)[2 * c];       // nodes 0..3 @ channel c
        float4 xb = reinterpret_cast<float4*>(xt)[2 * c + 1];   // nodes 4..7 @ channel c
        const uint64_t* wrow = reinterpret_cast<const uint64_t*>(w1s + c * 128);
        uint64_t wlo = wrow[2 * lane], whi = wrow[2 * lane + 1];
        uint64_t xx;
        PACKF2(xx, xa.x, xa.x);
        FMAF2(acc[0][0], xx, wlo, acc[0][0]); FMAF2(acc[0][1], xx, whi, acc[0][1]);
        PACKF2(xx, xa.y, xa.y);
        FMAF2(acc[1][0], xx, wlo, acc[1][0]); FMAF2(acc[1][1], xx, whi, acc[1][1]);
        PACKF2(xx, xa.z, xa.z);
        FMAF2(acc[2][0], xx, wlo, acc[2][0]); FMAF2(acc[2][1], xx, whi, acc[2][1]);
        PACKF2(xx, xa.w, xa.w);
        FMAF2(acc[3][0], xx, wlo, acc[3][0]); FMAF2(acc[3][1], xx, whi, acc[3][1]);
        PACKF2(xx, xb.x, xb.x);
        FMAF2(acc[4][0], xx, wlo, acc[4][0]); FMAF2(acc[4][1], xx, whi, acc[4][1]);
        PACKF2(xx, xb.y, xb.y);
        FMAF2(acc[5][0], xx, wlo, acc[5][0]); FMAF2(acc[5][1], xx, whi, acc[5][1]);
        PACKF2(xx, xb.z, xb.z);
        FMAF2(acc[6][0], xx, wlo, acc[6][0]); FMAF2(acc[6][1], xx, whi, acc[6][1]);
        PACKF2(xx, xb.w, xb.w);
        FMAF2(acc[7][0], xx, wlo, acc[7][0]); FMAF2(acc[7][1], xx, whi, acc[7][1]);
    }

    // silu + stage h (approx-div: ~2ulp, fine vs 1e-3 gate)
    #pragma unroll
    for (int u = 0; u < NPW; u++) {
        float4 v;
        UNPACKF2(v.x, v.y, acc[u][0]);
        UNPACKF2(v.z, v.w, acc[u][1]);
        v.x = __fdividef(v.x, 1.f + __expf(-v.x));
        v.y = __fdividef(v.y, 1.f + __expf(-v.y));
        v.z = __fdividef(v.z, 1.f + __expf(-v.z));
        v.w = __fdividef(v.w, 1.f + __expf(-v.w));
        reinterpret_cast<float4*>(hh + u * 128)[lane] = v;
    }
    __syncwarp();

    // Layer 2 (packed): p[u] = packed channels (2*lane, 2*lane+1) of node u.
    float2 bb2 = reinterpret_cast<const float2*>(b2)[lane];
    uint64_t pb;
    PACKF2(pb, bb2.x, bb2.y);
    uint64_t p[NPW];
    #pragma unroll
    for (int u = 0; u < NPW; u++) p[u] = pb;

    #pragma unroll 2
    for (int k4 = 0; k4 < 32; k4++) {
        float4 hv[NPW];
        #pragma unroll
        for (int u = 0; u < NPW; u++)
            hv[u] = reinterpret_cast<float4*>(hh + u * 128)[k4];
        #pragma unroll
        for (int j = 0; j < 4; j++) {
            uint64_t w = reinterpret_cast<const uint64_t*>(w2s + (4 * k4 + j) * 64)[lane];
            #pragma unroll
            for (int u = 0; u < NPW; u++) {
                float a = (j == 0) ? hv[u].x : (j == 1) ? hv[u].y
                        : (j == 2) ? hv[u].z : hv[u].w;
                uint64_t hb;
                PACKF2(hb, a, a);
                FMAF2(p[u], hb, w, p[u]);
            }
        }
    }

    // Epilogue: q[n,i,c] = vln[c] * p[n,c] * vec[n,i,c]
    float2 wv = reinterpret_cast<const float2*>(vw)[lane];
    #pragma unroll
    for (int u = 0; u < NPW; u++) {
        int n = node0 + u;
        if (n >= N) continue;
        float px, py;
        UNPACKF2(px, py, p[u]);
        float2 pw;
        pw.x = px * wv.x;
        pw.y = py * wv.y;
        const float2* vsrc = reinterpret_cast<const float2*>(vec + (size_t)n * 192);
        float2*       qdst = reinterpret_cast<float2*>(g_q + (size_t)n * 192);
        #pragma unroll
        for (int i = 0; i < 3; i++) {
            float2 v = vsrc[i * 32 + lane];
            float2 qq;
            qq.x = pw.x * v.x;
            qq.y = pw.y * v.y;
            qdst[i * 32 + lane] = qq;
        }
    }
}

// ---------------------------------------------------------------------------
// K2: per-edge phase, ILP-2: 16 lanes per group, 2 edges per group.
// ---------------------------------------------------------------------------
__device__ __forceinline__ float4 pole_energy(
    float mv,
    float4 qj0, float4 qj1, float4 qj2,
    float4 qi0, float4 qi1, float4 qi2)
{
    float m00 = __shfl_sync(0xffffffffu, mv, 0, 16);
    float m01 = __shfl_sync(0xffffffffu, mv, 1, 16);
    float m02 = __shfl_sync(0xffffffffu, mv, 2, 16);
    float m10 = __shfl_sync(0xffffffffu, mv, 3, 16);
    float m11 = __shfl_sync(0xffffffffu, mv, 4, 16);
    float m12 = __shfl_sync(0xffffffffu, mv, 5, 16);
    float m20 = __shfl_sync(0xffffffffu, mv, 6, 16);
    float m21 = __shfl_sync(0xffffffffu, mv, 7, 16);
    float m22 = __shfl_sync(0xffffffffu, mv, 8, 16);

    float4 f0, f1, f2, d;
    f0.x = m00 * qj0.x + m01 * qj1.x + m02 * qj2.x;
    f0.y = m00 * qj0.y + m01 * qj1.y + m02 * qj2.y;
    f0.z = m00 * qj0.z + m01 * qj1.z + m02 * qj2.z;
    f0.w = m00 * qj0.w + m01 * qj1.w + m02 * qj2.w;
    f1.x = m10 * qj0.x + m11 * qj1.x + m12 * qj2.x;
    f1.y = m10 * qj0.y + m11 * qj1.y + m12 * qj2.y;
    f1.z = m10 * qj0.z + m11 * qj1.z + m12 * qj2.z;
    f1.w = m10 * qj0.w + m11 * qj1.w + m12 * qj2.w;
    f2.x = m20 * qj0.x + m21 * qj1.x + m22 * qj2.x;
    f2.y = m20 * qj0.y + m21 * qj1.y + m22 * qj2.y;
    f2.z = m20 * qj0.z + m21 * qj1.z + m22 * qj2.z;
    f2.w = m20 * qj0.w + m21 * qj1.w + m22 * qj2.w;

    d.x = qi0.x * f0.x + qi1.x * f1.x + qi2.x * f2.x;
    d.y = qi0.y * f0.y + qi1.y * f1.y + qi2.y * f2.y;
    d.z = qi0.z * f0.z + qi1.z * f1.z + qi2.z * f2.z;
    d.w = qi0.w * f0.w + qi1.w * f1.w + qi2.w * f2.w;
    return d;
}

__global__ __launch_bounds__(256) void k_edge(
    const int*   __restrict__ senders,
    const int*   __restrict__ receivers,
    const float* __restrict__ Mm,
    float* __restrict__ out,
    int E)
{
    int t = blockIdx.x * blockDim.x + threadIdx.x;
    int g = t >> 4;
    int l = t & 15;
    int eA = g * 2;
    if (eA >= E) return;
    bool hasB = (eA + 1) < E;
    int eB = hasB ? eA + 1 : eA;

    int sA = __ldg(senders + eA), rA = __ldg(receivers + eA);
    int sB = __ldg(senders + eB), rB = __ldg(receivers + eB);

    float mvA = 0.f, mvB = 0.f;
    if (l < 9) {
        mvA = __ldg(Mm + (size_t)eA * 9 + l);
        mvB = __ldg(Mm + (size_t)eB * 9 + l);
    }

    const float4* qjA = reinterpret_cast<const float4*>(g_q + (size_t)sA * 192) + l;
    const float4* qiA = reinterpret_cast<const float4*>(g_q + (size_t)rA * 192) + l;
    const float4* qjB = reinterpret_cast<const float4*>(g_q + (size_t)sB * 192) + l;
    const float4* qiB = reinterpret_cast<const float4*>(g_q + (size_t)rB * 192) + l;

    float4 qjA0 = __ldg(qjA + 0), qjA1 = __ldg(qjA + 16), qjA2 = __ldg(qjA + 32);
    float4 qiA0 = __ldg(qiA + 0), qiA1 = __ldg(qiA + 16), qiA2 = __ldg(qiA + 32);
    float4 qjB0 = __ldg(qjB + 0), qjB1 = __ldg(qjB + 16), qjB2 = __ldg(qjB + 32);
    float4 qiB0 = __ldg(qiB + 0), qiB1 = __ldg(qiB + 16), qiB2 = __ldg(qiB + 32);

    float4 dA = pole_energy(mvA, qjA0, qjA1, qjA2, qiA0, qiA1, qiA2);
    {
        float* dst = out + (size_t)rA * 64 + 4 * l;
        asm volatile("red.global.add.v4.f32 [%0], {%1, %2, %3, %4};"
                     :: "l"(dst), "f"(dA.x), "f"(dA.y), "f"(dA.z), "f"(dA.w)
                     : "memory");
    }

    if (hasB) {
        float4 dB = pole_energy(mvB, qjB0, qjB1, qjB2, qiB0, qiB1, qiB2);
        float* dst = out + (size_t)rB * 64 + 4 * l;
        asm volatile("red.global.add.v4.f32 [%0], {%1, %2, %3, %4};"
                     :: "l"(dst), "f"(dB.x), "f"(dB.y), "f"(dB.z), "f"(dB.w)
                     : "memory");
    }
}

// ---------------------------------------------------------------------------
extern "C" void kernel_launch(void* const* d_in, const int* in_sizes, int n_in,
                              void* d_out, int out_size)
{
    const float* x         = (const float*)d_in[0];
    const float* vec       = (const float*)d_in[1];
    const int*   senders   = (const int*)  d_in[2];
    const int*   receivers = (const int*)  d_in[3];
    const float* im        = (const float*)d_in[4];
    const float* ln_scale  = (const float*)d_in[5];
    const float* ln_bias   = (const float*)d_in[6];
    const float* vln       = (const float*)d_in[7];
    const float* w1        = (const float*)d_in[8];
    const float* b1        = (const float*)d_in[9];
    const float* w2        = (const float*)d_in[10];
    const float* b2        = (const float*)d_in[11];

    int N = in_sizes[0] / CCH;
    int E = in_sizes[2];

    const int smem = (64 * 128 + 128 * 64 + K1_WARPS * 64 * NPW + K1_WARPS * NPW * 128)
                     * (int)sizeof(float);                       // 112 KB
    static bool attr_set = false;
    if (!attr_set) {
        cudaFuncSetAttribute(k_node, cudaFuncAttributeMaxDynamicSharedMemorySize, smem);
        attr_set = true;
    }
    int nodes_per_block = K1_WARPS * NPW;
    k_node<<<(N + nodes_per_block - 1) / nodes_per_block, 32 * K1_WARPS, smem>>>(
        x, vec, ln_scale, ln_bias, vln, w1, b1, w2, b2, (float*)d_out, N);

    int ngroups = (E + 1) / 2;                    // 2 edges per 16-lane group
    long long tot = (long long)ngroups * 16;
    int eblocks = (int)((tot + 255) / 256);
    k_edge<<<eblocks, 256>>>(senders, receivers, im, (float*)d_out, E);
}

// round 15
// speedup vs baseline: 2.2242x; 1.0456x over previous
#include <cuda_runtime.h>
#include <cuda_bf16.h>
#include <cstdint>

// PoleInteraction, q-fused form:
//   p = MLP(LayerNorm(x));  q[n,i,c] = vln[c]*p[n,c]*vec[n,i,c]
//   dEnergy[e,c] = sum_ij q[r,i,c]*M[e,i,j]*q[s,j,c]
//   dx = segment_sum(dEnergy, receivers)   (red.global.add.v4)
// k_node: persistent (weights loaded once/block), 8 nodes/warp, fma.rn.f32x2.

#define NODES_MAX 50000
#define CCH 64
#define K1_WARPS 8    // 256-thread blocks
#define NPW 8         // nodes per warp
#define K1_GRID 296   // 2 blocks/SM * 148 SMs: one persistent wave

__device__ float g_q[NODES_MAX * 3 * CCH];  // fused w*p*vec field [N,3,64]

// packed f32x2 helpers
#define PACKF2(d, lo, hi) \
    asm("mov.b64 %0, {%1, %2};" : "=l"(d) : "r"(__float_as_uint(lo)), "r"(__float_as_uint(hi)))
#define UNPACKF2(lo, hi, s) do { \
    unsigned _a, _b; \
    asm("mov.b64 {%0, %1}, %2;" : "=r"(_a), "=r"(_b) : "l"(s)); \
    lo = __uint_as_float(_a); hi = __uint_as_float(_b); } while (0)
#define FMAF2(d, a, b, c) \
    asm("fma.rn.f32x2 %0, %1, %2, %3;" : "=l"(d) : "l"(a), "l"(b), "l"(c))

// ---------------------------------------------------------------------------
// K1: persistent LayerNorm + MLP (64 -> 128 silu -> 64) + q epilogue + zeroing.
// 8 warps/block, 8 nodes/warp/tile; block grid-strides over 64-node tiles.
// ---------------------------------------------------------------------------
__global__ __launch_bounds__(32 * K1_WARPS) void k_node(
    const float* __restrict__ x,
    const float* __restrict__ vec,
    const float* __restrict__ ln_s, const float* __restrict__ ln_b,
    const float* __restrict__ vw,
    const float* __restrict__ w1, const float* __restrict__ b1,
    const float* __restrict__ w2, const float* __restrict__ b2,
    float* __restrict__ out,
    int N)
{
    extern __shared__ float sm[];
    float* w1s = sm;                          // 64*128
    float* w2s = w1s + 64 * 128;              // 128*64
    float* xts = w2s + 128 * 64;              // K1_WARPS * 64 ch * NPW (transposed)
    float* hs  = xts + K1_WARPS * 64 * NPW;   // K1_WARPS * NPW * 128

    int tid = threadIdx.x;
    for (int i = tid; i < (64 * 128) / 4; i += blockDim.x)
        reinterpret_cast<float4*>(w1s)[i] = reinterpret_cast<const float4*>(w1)[i];
    for (int i = tid; i < (128 * 64) / 4; i += blockDim.x)
        reinterpret_cast<float4*>(w2s)[i] = reinterpret_cast<const float4*>(w2)[i];
    __syncthreads();

    int warp = tid >> 5, lane = tid & 31;
    float* xt = xts + warp * 64 * NPW;    // xt[c*NPW + u]
    float* hh = hs  + warp * NPW * 128;   // hh[u*128 + k]

    float2 lns = reinterpret_cast<const float2*>(ln_s)[lane];
    float2 lnb = reinterpret_cast<const float2*>(ln_b)[lane];
    float4 bb1 = reinterpret_cast<const float4*>(b1)[lane];
    float2 bb2 = reinterpret_cast<const float2*>(b2)[lane];
    float2 wv  = reinterpret_cast<const float2*>(vw)[lane];
    uint64_t b1lo, b1hi, pb;
    PACKF2(b1lo, bb1.x, bb1.y);
    PACKF2(b1hi, bb1.z, bb1.w);
    PACKF2(pb, bb2.x, bb2.y);

    const int npb = K1_WARPS * NPW;           // nodes per block-tile
    const int ntiles = (N + npb - 1) / npb;

    for (int tile = blockIdx.x; tile < ntiles; tile += K1_GRID) {
        int node0 = (tile * K1_WARPS + warp) * NPW;
        if (node0 >= N) continue;

        // zero this warp's output rows (replaces the global memset)
        {
            int nvalid = min(NPW, N - node0);
            float4 z = make_float4(0.f, 0.f, 0.f, 0.f);
            float4* orow = reinterpret_cast<float4*>(out + (size_t)node0 * 64);
            for (int i = lane; i < nvalid * 16; i += 32) orow[i] = z;
        }

        // LayerNorm for NPW nodes; thread owns channels 2*lane, 2*lane+1.
        #pragma unroll
        for (int u = 0; u < NPW; u++) {
            int n = node0 + u;
            float2 v = make_float2(0.f, 0.f);
            if (n < N) v = reinterpret_cast<const float2*>(x + (size_t)n * 64)[lane];
            float s  = v.x + v.y;
            float sq = v.x * v.x + v.y * v.y;
            #pragma unroll
            for (int o = 16; o; o >>= 1) {
                s  += __shfl_xor_sync(0xffffffffu, s,  o);
                sq += __shfl_xor_sync(0xffffffffu, sq, o);
            }
            float mean = s * (1.f / 64.f);
            float var  = sq * (1.f / 64.f) - mean * mean;
            float rstd = rsqrtf(var + 1e-5f);
            xt[(2 * lane    ) * NPW + u] = (v.x - mean) * rstd * lns.x + lnb.x;
            xt[(2 * lane + 1) * NPW + u] = (v.y - mean) * rstd * lns.y + lnb.y;
        }
        __syncwarp();

        // Layer 1 (packed)
        uint64_t acc[NPW][2];
        #pragma unroll
        for (int u = 0; u < NPW; u++) { acc[u][0] = b1lo; acc[u][1] = b1hi; }

        #pragma unroll 2
        for (int c = 0; c < 64; c++) {
            float4 xa = reinterpret_cast<float4*>(xt)[2 * c];       // nodes 0..3
            float4 xb = reinterpret_cast<float4*>(xt)[2 * c + 1];   // nodes 4..7
            const uint64_t* wrow = reinterpret_cast<const uint64_t*>(w1s + c * 128);
            uint64_t wlo = wrow[2 * lane], whi = wrow[2 * lane + 1];
            uint64_t xx;
            PACKF2(xx, xa.x, xa.x);
            FMAF2(acc[0][0], xx, wlo, acc[0][0]); FMAF2(acc[0][1], xx, whi, acc[0][1]);
            PACKF2(xx, xa.y, xa.y);
            FMAF2(acc[1][0], xx, wlo, acc[1][0]); FMAF2(acc[1][1], xx, whi, acc[1][1]);
            PACKF2(xx, xa.z, xa.z);
            FMAF2(acc[2][0], xx, wlo, acc[2][0]); FMAF2(acc[2][1], xx, whi, acc[2][1]);
            PACKF2(xx, xa.w, xa.w);
            FMAF2(acc[3][0], xx, wlo, acc[3][0]); FMAF2(acc[3][1], xx, whi, acc[3][1]);
            PACKF2(xx, xb.x, xb.x);
            FMAF2(acc[4][0], xx, wlo, acc[4][0]); FMAF2(acc[4][1], xx, whi, acc[4][1]);
            PACKF2(xx, xb.y, xb.y);
            FMAF2(acc[5][0], xx, wlo, acc[5][0]); FMAF2(acc[5][1], xx, whi, acc[5][1]);
            PACKF2(xx, xb.z, xb.z);
            FMAF2(acc[6][0], xx, wlo, acc[6][0]); FMAF2(acc[6][1], xx, whi, acc[6][1]);
            PACKF2(xx, xb.w, xb.w);
            FMAF2(acc[7][0], xx, wlo, acc[7][0]); FMAF2(acc[7][1], xx, whi, acc[7][1]);
        }

        // silu + stage h
        #pragma unroll
        for (int u = 0; u < NPW; u++) {
            float4 v;
            UNPACKF2(v.x, v.y, acc[u][0]);
            UNPACKF2(v.z, v.w, acc[u][1]);
            v.x = __fdividef(v.x, 1.f + __expf(-v.x));
            v.y = __fdividef(v.y, 1.f + __expf(-v.y));
            v.z = __fdividef(v.z, 1.f + __expf(-v.z));
            v.w = __fdividef(v.w, 1.f + __expf(-v.w));
            reinterpret_cast<float4*>(hh + u * 128)[lane] = v;
        }
        __syncwarp();

        // Layer 2 (packed)
        uint64_t p[NPW];
        #pragma unroll
        for (int u = 0; u < NPW; u++) p[u] = pb;

        #pragma unroll 2
        for (int k4 = 0; k4 < 32; k4++) {
            float4 hv[NPW];
            #pragma unroll
            for (int u = 0; u < NPW; u++)
                hv[u] = reinterpret_cast<float4*>(hh + u * 128)[k4];
            #pragma unroll
            for (int j = 0; j < 4; j++) {
                uint64_t w = reinterpret_cast<const uint64_t*>(w2s + (4 * k4 + j) * 64)[lane];
                #pragma unroll
                for (int u = 0; u < NPW; u++) {
                    float a = (j == 0) ? hv[u].x : (j == 1) ? hv[u].y
                            : (j == 2) ? hv[u].z : hv[u].w;
                    uint64_t hb;
                    PACKF2(hb, a, a);
                    FMAF2(p[u], hb, w, p[u]);
                }
            }
        }

        // Epilogue: q[n,i,c] = vln[c] * p[n,c] * vec[n,i,c]
        #pragma unroll
        for (int u = 0; u < NPW; u++) {
            int n = node0 + u;
            if (n >= N) continue;
            float px, py;
            UNPACKF2(px, py, p[u]);
            float2 pw;
            pw.x = px * wv.x;
            pw.y = py * wv.y;
            const float2* vsrc = reinterpret_cast<const float2*>(vec + (size_t)n * 192);
            float2*       qdst = reinterpret_cast<float2*>(g_q + (size_t)n * 192);
            #pragma unroll
            for (int i = 0; i < 3; i++) {
                float2 v = vsrc[i * 32 + lane];
                float2 qq;
                qq.x = pw.x * v.x;
                qq.y = pw.y * v.y;
                qdst[i * 32 + lane] = qq;
            }
        }
        __syncwarp();
    }
}

// ---------------------------------------------------------------------------
// K2: per-edge phase, ILP-2: 16 lanes per group, 2 edges per group.
// ---------------------------------------------------------------------------
__device__ __forceinline__ float4 pole_energy(
    float mv,
    float4 qj0, float4 qj1, float4 qj2,
    float4 qi0, float4 qi1, float4 qi2)
{
    float m00 = __shfl_sync(0xffffffffu, mv, 0, 16);
    float m01 = __shfl_sync(0xffffffffu, mv, 1, 16);
    float m02 = __shfl_sync(0xffffffffu, mv, 2, 16);
    float m10 = __shfl_sync(0xffffffffu, mv, 3, 16);
    float m11 = __shfl_sync(0xffffffffu, mv, 4, 16);
    float m12 = __shfl_sync(0xffffffffu, mv, 5, 16);
    float m20 = __shfl_sync(0xffffffffu, mv, 6, 16);
    float m21 = __shfl_sync(0xffffffffu, mv, 7, 16);
    float m22 = __shfl_sync(0xffffffffu, mv, 8, 16);

    float4 f0, f1, f2, d;
    f0.x = m00 * qj0.x + m01 * qj1.x + m02 * qj2.x;
    f0.y = m00 * qj0.y + m01 * qj1.y + m02 * qj2.y;
    f0.z = m00 * qj0.z + m01 * qj1.z + m02 * qj2.z;
    f0.w = m00 * qj0.w + m01 * qj1.w + m02 * qj2.w;
    f1.x = m10 * qj0.x + m11 * qj1.x + m12 * qj2.x;
    f1.y = m10 * qj0.y + m11 * qj1.y + m12 * qj2.y;
    f1.z = m10 * qj0.z + m11 * qj1.z + m12 * qj2.z;
    f1.w = m10 * qj0.w + m11 * qj1.w + m12 * qj2.w;
    f2.x = m20 * qj0.x + m21 * qj1.x + m22 * qj2.x;
    f2.y = m20 * qj0.y + m21 * qj1.y + m22 * qj2.y;
    f2.z = m20 * qj0.z + m21 * qj1.z + m22 * qj2.z;
    f2.w = m20 * qj0.w + m21 * qj1.w + m22 * qj2.w;

    d.x = qi0.x * f0.x + qi1.x * f1.x + qi2.x * f2.x;
    d.y = qi0.y * f0.y + qi1.y * f1.y + qi2.y * f2.y;
    d.z = qi0.z * f0.z + qi1.z * f1.z + qi2.z * f2.z;
    d.w = qi0.w * f0.w + qi1.w * f1.w + qi2.w * f2.w;
    return d;
}

__global__ __launch_bounds__(256) void k_edge(
    const int*   __restrict__ senders,
    const int*   __restrict__ receivers,
    const float* __restrict__ Mm,
    float* __restrict__ out,
    int E)
{
    int t = blockIdx.x * blockDim.x + threadIdx.x;
    int g = t >> 4;
    int l = t & 15;
    int eA = g * 2;
    if (eA >= E) return;
    bool hasB = (eA + 1) < E;
    int eB = hasB ? eA + 1 : eA;

    int sA = __ldg(senders + eA), rA = __ldg(receivers + eA);
    int sB = __ldg(senders + eB), rB = __ldg(receivers + eB);

    float mvA = 0.f, mvB = 0.f;
    if (l < 9) {
        mvA = __ldg(Mm + (size_t)eA * 9 + l);
        mvB = __ldg(Mm + (size_t)eB * 9 + l);
    }

    const float4* qjA = reinterpret_cast<const float4*>(g_q + (size_t)sA * 192) + l;
    const float4* qiA = reinterpret_cast<const float4*>(g_q + (size_t)rA * 192) + l;
    const float4* qjB = reinterpret_cast<const float4*>(g_q + (size_t)sB * 192) + l;
    const float4* qiB = reinterpret_cast<const float4*>(g_q + (size_t)rB * 192) + l;

    float4 qjA0 = __ldg(qjA + 0), qjA1 = __ldg(qjA + 16), qjA2 = __ldg(qjA + 32);
    float4 qiA0 = __ldg(qiA + 0), qiA1 = __ldg(qiA + 16), qiA2 = __ldg(qiA + 32);
    float4 qjB0 = __ldg(qjB + 0), qjB1 = __ldg(qjB + 16), qjB2 = __ldg(qjB + 32);
    float4 qiB0 = __ldg(qiB + 0), qiB1 = __ldg(qiB + 16), qiB2 = __ldg(qiB + 32);

    float4 dA = pole_energy(mvA, qjA0, qjA1, qjA2, qiA0, qiA1, qiA2);
    {
        float* dst = out + (size_t)rA * 64 + 4 * l;
        asm volatile("red.global.add.v4.f32 [%0], {%1, %2, %3, %4};"
                     :: "l"(dst), "f"(dA.x), "f"(dA.y), "f"(dA.z), "f"(dA.w)
                     : "memory");
    }

    if (hasB) {
        float4 dB = pole_energy(mvB, qjB0, qjB1, qjB2, qiB0, qiB1, qiB2);
        float* dst = out + (size_t)rB * 64 + 4 * l;
        asm volatile("red.global.add.v4.f32 [%0], {%1, %2, %3, %4};"
                     :: "l"(dst), "f"(dB.x), "f"(dB.y), "f"(dB.z), "f"(dB.w)
                     : "memory");
    }
}

// ---------------------------------------------------------------------------
extern "C" void kernel_launch(void* const* d_in, const int* in_sizes, int n_in,
                              void* d_out, int out_size)
{
    const float* x         = (const float*)d_in[0];
    const float* vec       = (const float*)d_in[1];
    const int*   senders   = (const int*)  d_in[2];
    const int*   receivers = (const int*)  d_in[3];
    const float* im        = (const float*)d_in[4];
    const float* ln_scale  = (const float*)d_in[5];
    const float* ln_bias   = (const float*)d_in[6];
    const float* vln       = (const float*)d_in[7];
    const float* w1        = (const float*)d_in[8];
    const float* b1        = (const float*)d_in[9];
    const float* w2        = (const float*)d_in[10];
    const float* b2        = (const float*)d_in[11];

    int N = in_sizes[0] / CCH;
    int E = in_sizes[2];

    const int smem = (64 * 128 + 128 * 64 + K1_WARPS * 64 * NPW + K1_WARPS * NPW * 128)
                     * (int)sizeof(float);                       // 112 KB
    static bool attr_set = false;
    if (!attr_set) {
        cudaFuncSetAttribute(k_node, cudaFuncAttributeMaxDynamicSharedMemorySize, smem);
        attr_set = true;
    }
    k_node<<<K1_GRID, 32 * K1_WARPS, smem>>>(
        x, vec, ln_scale, ln_bias, vln, w1, b1, w2, b2, (float*)d_out, N);

    int ngroups = (E + 1) / 2;                    // 2 edges per 16-lane group
    long long tot = (long long)ngroups * 16;
    int eblocks = (int)((tot + 255) / 256);
    k_edge<<<eblocks, 256>>>(senders, receivers, im, (float*)d_out, E);
}

// round 16
// speedup vs baseline: 2.5022x; 1.1250x over previous
#include <cuda_runtime.h>
#include <cuda_bf16.h>
#include <cuda_fp16.h>
#include <cstdint>

// PoleInteraction, q-fused form with fp16 q storage:
//   p = MLP(LayerNorm(x));  q[n,i,c] = vln[c]*p[n,c]*vec[n,i,c]   (stored fp16)
//   dEnergy[e,c] = sum_ij q[r,i,c]*M[e,i,j]*q[s,j,c]              (fp32 math)
//   dx = segment_sum(dEnergy, receivers)   (red.global.add.v4, fp32)
// fp16 q halves the edge-phase gather traffic: each (node, xyz-component)
// row is exactly one 128B line.

#define NODES_MAX 50000
#define CCH 64
#define K1_WARPS 8    // 256-thread blocks
#define NPW 8         // nodes per warp
#define K1_GRID 296   // 2 blocks/SM * 148 SMs: one persistent wave

__device__ __half g_qh[NODES_MAX * 3 * CCH];  // fused w*p*vec field, fp16 [N,3,64]

// packed f32x2 helpers
#define PACKF2(d, lo, hi) \
    asm("mov.b64 %0, {%1, %2};" : "=l"(d) : "r"(__float_as_uint(lo)), "r"(__float_as_uint(hi)))
#define UNPACKF2(lo, hi, s) do { \
    unsigned _a, _b; \
    asm("mov.b64 {%0, %1}, %2;" : "=r"(_a), "=r"(_b) : "l"(s)); \
    lo = __uint_as_float(_a); hi = __uint_as_float(_b); } while (0)
#define FMAF2(d, a, b, c) \
    asm("fma.rn.f32x2 %0, %1, %2, %3;" : "=l"(d) : "l"(a), "l"(b), "l"(c))

// ---------------------------------------------------------------------------
// K1: persistent LayerNorm + MLP (64 -> 128 silu -> 64) + q epilogue + zeroing.
// ---------------------------------------------------------------------------
__global__ __launch_bounds__(32 * K1_WARPS) void k_node(
    const float* __restrict__ x,
    const float* __restrict__ vec,
    const float* __restrict__ ln_s, const float* __restrict__ ln_b,
    const float* __restrict__ vw,
    const float* __restrict__ w1, const float* __restrict__ b1,
    const float* __restrict__ w2, const float* __restrict__ b2,
    float* __restrict__ out,
    int N)
{
    extern __shared__ float sm[];
    float* w1s = sm;                          // 64*128
    float* w2s = w1s + 64 * 128;              // 128*64
    float* xts = w2s + 128 * 64;              // K1_WARPS * 64 ch * NPW (transposed)
    float* hs  = xts + K1_WARPS * 64 * NPW;   // K1_WARPS * NPW * 128

    int tid = threadIdx.x;
    for (int i = tid; i < (64 * 128) / 4; i += blockDim.x)
        reinterpret_cast<float4*>(w1s)[i] = reinterpret_cast<const float4*>(w1)[i];
    for (int i = tid; i < (128 * 64) / 4; i += blockDim.x)
        reinterpret_cast<float4*>(w2s)[i] = reinterpret_cast<const float4*>(w2)[i];
    __syncthreads();

    int warp = tid >> 5, lane = tid & 31;
    float* xt = xts + warp * 64 * NPW;    // xt[c*NPW + u]
    float* hh = hs  + warp * NPW * 128;   // hh[u*128 + k]

    float2 lns = reinterpret_cast<const float2*>(ln_s)[lane];
    float2 lnb = reinterpret_cast<const float2*>(ln_b)[lane];
    float4 bb1 = reinterpret_cast<const float4*>(b1)[lane];
    float2 bb2 = reinterpret_cast<const float2*>(b2)[lane];
    float2 wv  = reinterpret_cast<const float2*>(vw)[lane];
    uint64_t b1lo, b1hi, pb;
    PACKF2(b1lo, bb1.x, bb1.y);
    PACKF2(b1hi, bb1.z, bb1.w);
    PACKF2(pb, bb2.x, bb2.y);

    const int npb = K1_WARPS * NPW;           // nodes per block-tile
    const int ntiles = (N + npb - 1) / npb;

    for (int tile = blockIdx.x; tile < ntiles; tile += K1_GRID) {
        int node0 = (tile * K1_WARPS + warp) * NPW;
        if (node0 >= N) continue;

        // zero this warp's output rows (replaces the global memset)
        {
            int nvalid = min(NPW, N - node0);
            float4 z = make_float4(0.f, 0.f, 0.f, 0.f);
            float4* orow = reinterpret_cast<float4*>(out + (size_t)node0 * 64);
            for (int i = lane; i < nvalid * 16; i += 32) orow[i] = z;
        }

        // LayerNorm for NPW nodes; thread owns channels 2*lane, 2*lane+1.
        #pragma unroll
        for (int u = 0; u < NPW; u++) {
            int n = node0 + u;
            float2 v = make_float2(0.f, 0.f);
            if (n < N) v = reinterpret_cast<const float2*>(x + (size_t)n * 64)[lane];
            float s  = v.x + v.y;
            float sq = v.x * v.x + v.y * v.y;
            #pragma unroll
            for (int o = 16; o; o >>= 1) {
                s  += __shfl_xor_sync(0xffffffffu, s,  o);
                sq += __shfl_xor_sync(0xffffffffu, sq, o);
            }
            float mean = s * (1.f / 64.f);
            float var  = sq * (1.f / 64.f) - mean * mean;
            float rstd = rsqrtf(var + 1e-5f);
            xt[(2 * lane    ) * NPW + u] = (v.x - mean) * rstd * lns.x + lnb.x;
            xt[(2 * lane + 1) * NPW + u] = (v.y - mean) * rstd * lns.y + lnb.y;
        }
        __syncwarp();

        // Layer 1 (packed)
        uint64_t acc[NPW][2];
        #pragma unroll
        for (int u = 0; u < NPW; u++) { acc[u][0] = b1lo; acc[u][1] = b1hi; }

        #pragma unroll 2
        for (int c = 0; c < 64; c++) {
            float4 xa = reinterpret_cast<float4*>(xt)[2 * c];       // nodes 0..3
            float4 xb = reinterpret_cast<float4*>(xt)[2 * c + 1];   // nodes 4..7
            const uint64_t* wrow = reinterpret_cast<const uint64_t*>(w1s + c * 128);
            uint64_t wlo = wrow[2 * lane], whi = wrow[2 * lane + 1];
            uint64_t xx;
            PACKF2(xx, xa.x, xa.x);
            FMAF2(acc[0][0], xx, wlo, acc[0][0]); FMAF2(acc[0][1], xx, whi, acc[0][1]);
            PACKF2(xx, xa.y, xa.y);
            FMAF2(acc[1][0], xx, wlo, acc[1][0]); FMAF2(acc[1][1], xx, whi, acc[1][1]);
            PACKF2(xx, xa.z, xa.z);
            FMAF2(acc[2][0], xx, wlo, acc[2][0]); FMAF2(acc[2][1], xx, whi, acc[2][1]);
            PACKF2(xx, xa.w, xa.w);
            FMAF2(acc[3][0], xx, wlo, acc[3][0]); FMAF2(acc[3][1], xx, whi, acc[3][1]);
            PACKF2(xx, xb.x, xb.x);
            FMAF2(acc[4][0], xx, wlo, acc[4][0]); FMAF2(acc[4][1], xx, whi, acc[4][1]);
            PACKF2(xx, xb.y, xb.y);
            FMAF2(acc[5][0], xx, wlo, acc[5][0]); FMAF2(acc[5][1], xx, whi, acc[5][1]);
            PACKF2(xx, xb.z, xb.z);
            FMAF2(acc[6][0], xx, wlo, acc[6][0]); FMAF2(acc[6][1], xx, whi, acc[6][1]);
            PACKF2(xx, xb.w, xb.w);
            FMAF2(acc[7][0], xx, wlo, acc[7][0]); FMAF2(acc[7][1], xx, whi, acc[7][1]);
        }

        // silu + stage h
        #pragma unroll
        for (int u = 0; u < NPW; u++) {
            float4 v;
            UNPACKF2(v.x, v.y, acc[u][0]);
            UNPACKF2(v.z, v.w, acc[u][1]);
            v.x = __fdividef(v.x, 1.f + __expf(-v.x));
            v.y = __fdividef(v.y, 1.f + __expf(-v.y));
            v.z = __fdividef(v.z, 1.f + __expf(-v.z));
            v.w = __fdividef(v.w, 1.f + __expf(-v.w));
            reinterpret_cast<float4*>(hh + u * 128)[lane] = v;
        }
        __syncwarp();

        // Layer 2 (packed)
        uint64_t p[NPW];
        #pragma unroll
        for (int u = 0; u < NPW; u++) p[u] = pb;

        #pragma unroll 2
        for (int k4 = 0; k4 < 32; k4++) {
            float4 hv[NPW];
            #pragma unroll
            for (int u = 0; u < NPW; u++)
                hv[u] = reinterpret_cast<float4*>(hh + u * 128)[k4];
            #pragma unroll
            for (int j = 0; j < 4; j++) {
                uint64_t w = reinterpret_cast<const uint64_t*>(w2s + (4 * k4 + j) * 64)[lane];
                #pragma unroll
                for (int u = 0; u < NPW; u++) {
                    float a = (j == 0) ? hv[u].x : (j == 1) ? hv[u].y
                            : (j == 2) ? hv[u].z : hv[u].w;
                    uint64_t hb;
                    PACKF2(hb, a, a);
                    FMAF2(p[u], hb, w, p[u]);
                }
            }
        }

        // Epilogue: q[n,i,c] = vln[c] * p[n,c] * vec[n,i,c], stored as fp16.
        #pragma unroll
        for (int u = 0; u < NPW; u++) {
            int n = node0 + u;
            if (n >= N) continue;
            float px, py;
            UNPACKF2(px, py, p[u]);
            float2 pw;
            pw.x = px * wv.x;
            pw.y = py * wv.y;
            const float2* vsrc = reinterpret_cast<const float2*>(vec + (size_t)n * 192);
            __half2*      qdst = reinterpret_cast<__half2*>(g_qh + (size_t)n * 192);
            #pragma unroll
            for (int i = 0; i < 3; i++) {
                float2 v = vsrc[i * 32 + lane];
                float2 qq;
                qq.x = pw.x * v.x;
                qq.y = pw.y * v.y;
                qdst[i * 32 + lane] = __float22half2_rn(qq);
            }
        }
        __syncwarp();
    }
}

// ---------------------------------------------------------------------------
// K2: per-edge phase, ILP-2: 16 lanes per group, 2 edges per group.
// q gathered as fp16 (uint2 = 4 halfs per lane per component = one 128B line
// per (node, component) per 16-lane group), converted to fp32 for the math.
// ---------------------------------------------------------------------------
__device__ __forceinline__ float4 h4_to_f4(uint2 u)
{
    __half2 h0 = *reinterpret_cast<__half2*>(&u.x);
    __half2 h1 = *reinterpret_cast<__half2*>(&u.y);
    float2 lo = __half22float2(h0);
    float2 hi = __half22float2(h1);
    return make_float4(lo.x, lo.y, hi.x, hi.y);
}

__device__ __forceinline__ float4 pole_energy(
    float mv,
    uint2 j0, uint2 j1, uint2 j2,
    uint2 i0, uint2 i1, uint2 i2)
{
    float m00 = __shfl_sync(0xffffffffu, mv, 0, 16);
    float m01 = __shfl_sync(0xffffffffu, mv, 1, 16);
    float m02 = __shfl_sync(0xffffffffu, mv, 2, 16);
    float m10 = __shfl_sync(0xffffffffu, mv, 3, 16);
    float m11 = __shfl_sync(0xffffffffu, mv, 4, 16);
    float m12 = __shfl_sync(0xffffffffu, mv, 5, 16);
    float m20 = __shfl_sync(0xffffffffu, mv, 6, 16);
    float m21 = __shfl_sync(0xffffffffu, mv, 7, 16);
    float m22 = __shfl_sync(0xffffffffu, mv, 8, 16);

    float4 qj0 = h4_to_f4(j0), qj1 = h4_to_f4(j1), qj2 = h4_to_f4(j2);
    float4 qi0 = h4_to_f4(i0), qi1 = h4_to_f4(i1), qi2 = h4_to_f4(i2);

    float4 f0, f1, f2, d;
    f0.x = m00 * qj0.x + m01 * qj1.x + m02 * qj2.x;
    f0.y = m00 * qj0.y + m01 * qj1.y + m02 * qj2.y;
    f0.z = m00 * qj0.z + m01 * qj1.z + m02 * qj2.z;
    f0.w = m00 * qj0.w + m01 * qj1.w + m02 * qj2.w;
    f1.x = m10 * qj0.x + m11 * qj1.x + m12 * qj2.x;
    f1.y = m10 * qj0.y + m11 * qj1.y + m12 * qj2.y;
    f1.z = m10 * qj0.z + m11 * qj1.z + m12 * qj2.z;
    f1.w = m10 * qj0.w + m11 * qj1.w + m12 * qj2.w;
    f2.x = m20 * qj0.x + m21 * qj1.x + m22 * qj2.x;
    f2.y = m20 * qj0.y + m21 * qj1.y + m22 * qj2.y;
    f2.z = m20 * qj0.z + m21 * qj1.z + m22 * qj2.z;
    f2.w = m20 * qj0.w + m21 * qj1.w + m22 * qj2.w;

    d.x = qi0.x * f0.x + qi1.x * f1.x + qi2.x * f2.x;
    d.y = qi0.y * f0.y + qi1.y * f1.y + qi2.y * f2.y;
    d.z = qi0.z * f0.z + qi1.z * f1.z + qi2.z * f2.z;
    d.w = qi0.w * f0.w + qi1.w * f1.w + qi2.w * f2.w;
    return d;
}

__global__ __launch_bounds__(256) void k_edge(
    const int*   __restrict__ senders,
    const int*   __restrict__ receivers,
    const float* __restrict__ Mm,
    float* __restrict__ out,
    int E)
{
    int t = blockIdx.x * blockDim.x + threadIdx.x;
    int g = t >> 4;
    int l = t & 15;
    int eA = g * 2;
    if (eA >= E) return;
    bool hasB = (eA + 1) < E;
    int eB = hasB ? eA + 1 : eA;

    int sA = __ldg(senders + eA), rA = __ldg(receivers + eA);
    int sB = __ldg(senders + eB), rB = __ldg(receivers + eB);

    float mvA = 0.f, mvB = 0.f;
    if (l < 9) {
        mvA = __ldg(Mm + (size_t)eA * 9 + l);
        mvB = __ldg(Mm + (size_t)eB * 9 + l);
    }

    // q rows: 192 halfs = 48 uint2; one component = 16 uint2 = 128B.
    const uint2* qjA = reinterpret_cast<const uint2*>(g_qh + (size_t)sA * 192) + l;
    const uint2* qiA = reinterpret_cast<const uint2*>(g_qh + (size_t)rA * 192) + l;
    const uint2* qjB = reinterpret_cast<const uint2*>(g_qh + (size_t)sB * 192) + l;
    const uint2* qiB = reinterpret_cast<const uint2*>(g_qh + (size_t)rB * 192) + l;

    uint2 jA0 = __ldg(qjA + 0), jA1 = __ldg(qjA + 16), jA2 = __ldg(qjA + 32);
    uint2 iA0 = __ldg(qiA + 0), iA1 = __ldg(qiA + 16), iA2 = __ldg(qiA + 32);
    uint2 jB0 = __ldg(qjB + 0), jB1 = __ldg(qjB + 16), jB2 = __ldg(qjB + 32);
    uint2 iB0 = __ldg(qiB + 0), iB1 = __ldg(qiB + 16), iB2 = __ldg(qiB + 32);

    float4 dA = pole_energy(mvA, jA0, jA1, jA2, iA0, iA1, iA2);
    {
        float* dst = out + (size_t)rA * 64 + 4 * l;
        asm volatile("red.global.add.v4.f32 [%0], {%1, %2, %3, %4};"
                     :: "l"(dst), "f"(dA.x), "f"(dA.y), "f"(dA.z), "f"(dA.w)
                     : "memory");
    }

    if (hasB) {
        float4 dB = pole_energy(mvB, jB0, jB1, jB2, iB0, iB1, iB2);
        float* dst = out + (size_t)rB * 64 + 4 * l;
        asm volatile("red.global.add.v4.f32 [%0], {%1, %2, %3, %4};"
                     :: "l"(dst), "f"(dB.x), "f"(dB.y), "f"(dB.z), "f"(dB.w)
                     : "memory");
    }
}

// ---------------------------------------------------------------------------
extern "C" void kernel_launch(void* const* d_in, const int* in_sizes, int n_in,
                              void* d_out, int out_size)
{
    const float* x         = (const float*)d_in[0];
    const float* vec       = (const float*)d_in[1];
    const int*   senders   = (const int*)  d_in[2];
    const int*   receivers = (const int*)  d_in[3];
    const float* im        = (const float*)d_in[4];
    const float* ln_scale  = (const float*)d_in[5];
    const float* ln_bias   = (const float*)d_in[6];
    const float* vln       = (const float*)d_in[7];
    const float* w1        = (const float*)d_in[8];
    const float* b1        = (const float*)d_in[9];
    const float* w2        = (const float*)d_in[10];
    const float* b2        = (const float*)d_in[11];

    int N = in_sizes[0] / CCH;
    int E = in_sizes[2];

    const int smem = (64 * 128 + 128 * 64 + K1_WARPS * 64 * NPW + K1_WARPS * NPW * 128)
                     * (int)sizeof(float);                       // 112 KB
    static bool attr_set = false;
    if (!attr_set) {
        cudaFuncSetAttribute(k_node, cudaFuncAttributeMaxDynamicSharedMemorySize, smem);
        attr_set = true;
    }
    k_node<<<K1_GRID, 32 * K1_WARPS, smem>>>(
        x, vec, ln_scale, ln_bias, vln, w1, b1, w2, b2, (float*)d_out, N);

    int ngroups = (E + 1) / 2;                    // 2 edges per 16-lane group
    long long tot = (long long)ngroups * 16;
    int eblocks = (int)((tot + 255) / 256);
    k_edge<<<eblocks, 256>>>(senders, receivers, im, (float*)d_out, E);
}

// round 17
// speedup vs baseline: 2.6413x; 1.0556x over previous
#include <cuda_runtime.h>
#include <cuda_bf16.h>
#include <cuda_fp16.h>
#include <cstdint>

// PoleInteraction, q-fused form with fp16 q storage AND fp16 edge math:
//   p = MLP(LayerNorm(x));  q[n,i,c] = vln[c]*p[n,c]*vec[n,i,c]   (stored fp16)
//   dEnergy[e,c] = sum_ij q[r,i,c]*M[e,i,j]*q[s,j,c]              (HFMA2 math)
//   dx = segment_sum(dEnergy, receivers)   (red.global.add.v4, fp32)

#define NODES_MAX 50000
#define CCH 64
#define K1_WARPS 8    // 256-thread blocks
#define NPW 8         // nodes per warp
#define K1_GRID 296   // 2 blocks/SM * 148 SMs: one persistent wave

__device__ __half g_qh[NODES_MAX * 3 * CCH];  // fused w*p*vec field, fp16 [N,3,64]

// packed f32x2 helpers
#define PACKF2(d, lo, hi) \
    asm("mov.b64 %0, {%1, %2};" : "=l"(d) : "r"(__float_as_uint(lo)), "r"(__float_as_uint(hi)))
#define UNPACKF2(lo, hi, s) do { \
    unsigned _a, _b; \
    asm("mov.b64 {%0, %1}, %2;" : "=r"(_a), "=r"(_b) : "l"(s)); \
    lo = __uint_as_float(_a); hi = __uint_as_float(_b); } while (0)
#define FMAF2(d, a, b, c) \
    asm("fma.rn.f32x2 %0, %1, %2, %3;" : "=l"(d) : "l"(a), "l"(b), "l"(c))

// ---------------------------------------------------------------------------
// K1: persistent LayerNorm + MLP (64 -> 128 silu -> 64) + q epilogue + zeroing.
// ---------------------------------------------------------------------------
__global__ __launch_bounds__(32 * K1_WARPS) void k_node(
    const float* __restrict__ x,
    const float* __restrict__ vec,
    const float* __restrict__ ln_s, const float* __restrict__ ln_b,
    const float* __restrict__ vw,
    const float* __restrict__ w1, const float* __restrict__ b1,
    const float* __restrict__ w2, const float* __restrict__ b2,
    float* __restrict__ out,
    int N)
{
    extern __shared__ float sm[];
    float* w1s = sm;                          // 64*128
    float* w2s = w1s + 64 * 128;              // 128*64
    float* xts = w2s + 128 * 64;              // K1_WARPS * 64 ch * NPW (transposed)
    float* hs  = xts + K1_WARPS * 64 * NPW;   // K1_WARPS * NPW * 128

    int tid = threadIdx.x;
    for (int i = tid; i < (64 * 128) / 4; i += blockDim.x)
        reinterpret_cast<float4*>(w1s)[i] = reinterpret_cast<const float4*>(w1)[i];
    for (int i = tid; i < (128 * 64) / 4; i += blockDim.x)
        reinterpret_cast<float4*>(w2s)[i] = reinterpret_cast<const float4*>(w2)[i];
    __syncthreads();

    int warp = tid >> 5, lane = tid & 31;
    float* xt = xts + warp * 64 * NPW;    // xt[c*NPW + u]
    float* hh = hs  + warp * NPW * 128;   // hh[u*128 + k]

    float2 lns = reinterpret_cast<const float2*>(ln_s)[lane];
    float2 lnb = reinterpret_cast<const float2*>(ln_b)[lane];
    float4 bb1 = reinterpret_cast<const float4*>(b1)[lane];
    float2 bb2 = reinterpret_cast<const float2*>(b2)[lane];
    float2 wv  = reinterpret_cast<const float2*>(vw)[lane];
    uint64_t b1lo, b1hi, pb;
    PACKF2(b1lo, bb1.x, bb1.y);
    PACKF2(b1hi, bb1.z, bb1.w);
    PACKF2(pb, bb2.x, bb2.y);

    const int npb = K1_WARPS * NPW;           // nodes per block-tile
    const int ntiles = (N + npb - 1) / npb;

    for (int tile = blockIdx.x; tile < ntiles; tile += K1_GRID) {
        int node0 = (tile * K1_WARPS + warp) * NPW;
        if (node0 >= N) continue;

        // zero this warp's output rows (replaces the global memset)
        {
            int nvalid = min(NPW, N - node0);
            float4 z = make_float4(0.f, 0.f, 0.f, 0.f);
            float4* orow = reinterpret_cast<float4*>(out + (size_t)node0 * 64);
            for (int i = lane; i < nvalid * 16; i += 32) orow[i] = z;
        }

        // LayerNorm for NPW nodes; thread owns channels 2*lane, 2*lane+1.
        #pragma unroll
        for (int u = 0; u < NPW; u++) {
            int n = node0 + u;
            float2 v = make_float2(0.f, 0.f);
            if (n < N) v = reinterpret_cast<const float2*>(x + (size_t)n * 64)[lane];
            float s  = v.x + v.y;
            float sq = v.x * v.x + v.y * v.y;
            #pragma unroll
            for (int o = 16; o; o >>= 1) {
                s  += __shfl_xor_sync(0xffffffffu, s,  o);
                sq += __shfl_xor_sync(0xffffffffu, sq, o);
            }
            float mean = s * (1.f / 64.f);
            float var  = sq * (1.f / 64.f) - mean * mean;
            float rstd = rsqrtf(var + 1e-5f);
            xt[(2 * lane    ) * NPW + u] = (v.x - mean) * rstd * lns.x + lnb.x;
            xt[(2 * lane + 1) * NPW + u] = (v.y - mean) * rstd * lns.y + lnb.y;
        }
        __syncwarp();

        // Layer 1 (packed)
        uint64_t acc[NPW][2];
        #pragma unroll
        for (int u = 0; u < NPW; u++) { acc[u][0] = b1lo; acc[u][1] = b1hi; }

        #pragma unroll 2
        for (int c = 0; c < 64; c++) {
            float4 xa = reinterpret_cast<float4*>(xt)[2 * c];       // nodes 0..3
            float4 xb = reinterpret_cast<float4*>(xt)[2 * c + 1];   // nodes 4..7
            const uint64_t* wrow = reinterpret_cast<const uint64_t*>(w1s + c * 128);
            uint64_t wlo = wrow[2 * lane], whi = wrow[2 * lane + 1];
            uint64_t xx;
            PACKF2(xx, xa.x, xa.x);
            FMAF2(acc[0][0], xx, wlo, acc[0][0]); FMAF2(acc[0][1], xx, whi, acc[0][1]);
            PACKF2(xx, xa.y, xa.y);
            FMAF2(acc[1][0], xx, wlo, acc[1][0]); FMAF2(acc[1][1], xx, whi, acc[1][1]);
            PACKF2(xx, xa.z, xa.z);
            FMAF2(acc[2][0], xx, wlo, acc[2][0]); FMAF2(acc[2][1], xx, whi, acc[2][1]);
            PACKF2(xx, xa.w, xa.w);
            FMAF2(acc[3][0], xx, wlo, acc[3][0]); FMAF2(acc[3][1], xx, whi, acc[3][1]);
            PACKF2(xx, xb.x, xb.x);
            FMAF2(acc[4][0], xx, wlo, acc[4][0]); FMAF2(acc[4][1], xx, whi, acc[4][1]);
            PACKF2(xx, xb.y, xb.y);
            FMAF2(acc[5][0], xx, wlo, acc[5][0]); FMAF2(acc[5][1], xx, whi, acc[5][1]);
            PACKF2(xx, xb.z, xb.z);
            FMAF2(acc[6][0], xx, wlo, acc[6][0]); FMAF2(acc[6][1], xx, whi, acc[6][1]);
            PACKF2(xx, xb.w, xb.w);
            FMAF2(acc[7][0], xx, wlo, acc[7][0]); FMAF2(acc[7][1], xx, whi, acc[7][1]);
        }

        // silu + stage h
        #pragma unroll
        for (int u = 0; u < NPW; u++) {
            float4 v;
            UNPACKF2(v.x, v.y, acc[u][0]);
            UNPACKF2(v.z, v.w, acc[u][1]);
            v.x = __fdividef(v.x, 1.f + __expf(-v.x));
            v.y = __fdividef(v.y, 1.f + __expf(-v.y));
            v.z = __fdividef(v.z, 1.f + __expf(-v.z));
            v.w = __fdividef(v.w, 1.f + __expf(-v.w));
            reinterpret_cast<float4*>(hh + u * 128)[lane] = v;
        }
        __syncwarp();

        // Layer 2 (packed)
        uint64_t p[NPW];
        #pragma unroll
        for (int u = 0; u < NPW; u++) p[u] = pb;

        #pragma unroll 2
        for (int k4 = 0; k4 < 32; k4++) {
            float4 hv[NPW];
            #pragma unroll
            for (int u = 0; u < NPW; u++)
                hv[u] = reinterpret_cast<float4*>(hh + u * 128)[k4];
            #pragma unroll
            for (int j = 0; j < 4; j++) {
                uint64_t w = reinterpret_cast<const uint64_t*>(w2s + (4 * k4 + j) * 64)[lane];
                #pragma unroll
                for (int u = 0; u < NPW; u++) {
                    float a = (j == 0) ? hv[u].x : (j == 1) ? hv[u].y
                            : (j == 2) ? hv[u].z : hv[u].w;
                    uint64_t hb;
                    PACKF2(hb, a, a);
                    FMAF2(p[u], hb, w, p[u]);
                }
            }
        }

        // Epilogue: q[n,i,c] = vln[c] * p[n,c] * vec[n,i,c], stored as fp16.
        #pragma unroll
        for (int u = 0; u < NPW; u++) {
            int n = node0 + u;
            if (n >= N) continue;
            float px, py;
            UNPACKF2(px, py, p[u]);
            float2 pw;
            pw.x = px * wv.x;
            pw.y = py * wv.y;
            const float2* vsrc = reinterpret_cast<const float2*>(vec + (size_t)n * 192);
            __half2*      qdst = reinterpret_cast<__half2*>(g_qh + (size_t)n * 192);
            #pragma unroll
            for (int i = 0; i < 3; i++) {
                float2 v = vsrc[i * 32 + lane];
                float2 qq;
                qq.x = pw.x * v.x;
                qq.y = pw.y * v.y;
                qdst[i * 32 + lane] = __float22half2_rn(qq);
            }
        }
        __syncwarp();
    }
}

// ---------------------------------------------------------------------------
// K2: per-edge phase, ILP-2, fully packed fp16 math (HMUL2/HFMA2).
// Only the final 4 output channels are widened to fp32 for the atomic.
// ---------------------------------------------------------------------------
__device__ __forceinline__ __half2 u2h(unsigned u) { return *reinterpret_cast<__half2*>(&u); }

// per-edge quadratic form on 4 channels (2x half2), fp16 throughout
__device__ __forceinline__ float4 pole_energy_h(
    unsigned mh,                       // lane l<9 holds half2(m_l, m_l)
    uint2 j0, uint2 j1, uint2 j2,      // q_sender  (3 comps x 4 halfs)
    uint2 i0, uint2 i1, uint2 i2)      // q_receiver
{
    __half2 m00 = u2h(__shfl_sync(0xffffffffu, mh, 0, 16));
    __half2 m01 = u2h(__shfl_sync(0xffffffffu, mh, 1, 16));
    __half2 m02 = u2h(__shfl_sync(0xffffffffu, mh, 2, 16));
    __half2 m10 = u2h(__shfl_sync(0xffffffffu, mh, 3, 16));
    __half2 m11 = u2h(__shfl_sync(0xffffffffu, mh, 4, 16));
    __half2 m12 = u2h(__shfl_sync(0xffffffffu, mh, 5, 16));
    __half2 m20 = u2h(__shfl_sync(0xffffffffu, mh, 6, 16));
    __half2 m21 = u2h(__shfl_sync(0xffffffffu, mh, 7, 16));
    __half2 m22 = u2h(__shfl_sync(0xffffffffu, mh, 8, 16));

    __half2 j0a = u2h(j0.x), j0b = u2h(j0.y);
    __half2 j1a = u2h(j1.x), j1b = u2h(j1.y);
    __half2 j2a = u2h(j2.x), j2b = u2h(j2.y);
    __half2 i0a = u2h(i0.x), i0b = u2h(i0.y);
    __half2 i1a = u2h(i1.x), i1b = u2h(i1.y);
    __half2 i2a = u2h(i2.x), i2b = u2h(i2.y);

    __half2 f0a = __hfma2(m02, j2a, __hfma2(m01, j1a, __hmul2(m00, j0a)));
    __half2 f0b = __hfma2(m02, j2b, __hfma2(m01, j1b, __hmul2(m00, j0b)));
    __half2 f1a = __hfma2(m12, j2a, __hfma2(m11, j1a, __hmul2(m10, j0a)));
    __half2 f1b = __hfma2(m12, j2b, __hfma2(m11, j1b, __hmul2(m10, j0b)));
    __half2 f2a = __hfma2(m22, j2a, __hfma2(m21, j1a, __hmul2(m20, j0a)));
    __half2 f2b = __hfma2(m22, j2b, __hfma2(m21, j1b, __hmul2(m20, j0b)));

    __half2 da = __hfma2(i2a, f2a, __hfma2(i1a, f1a, __hmul2(i0a, f0a)));
    __half2 db = __hfma2(i2b, f2b, __hfma2(i1b, f1b, __hmul2(i0b, f0b)));

    float2 lo = __half22float2(da);
    float2 hi = __half22float2(db);
    return make_float4(lo.x, lo.y, hi.x, hi.y);
}

__global__ __launch_bounds__(256) void k_edge(
    const int*   __restrict__ senders,
    const int*   __restrict__ receivers,
    const float* __restrict__ Mm,
    float* __restrict__ out,
    int E)
{
    int t = blockIdx.x * blockDim.x + threadIdx.x;
    int g = t >> 4;
    int l = t & 15;
    int eA = g * 2;
    if (eA >= E) return;
    bool hasB = (eA + 1) < E;
    int eB = hasB ? eA + 1 : eA;

    int sA = __ldg(senders + eA), rA = __ldg(receivers + eA);
    int sB = __ldg(senders + eB), rB = __ldg(receivers + eB);

    unsigned mhA = 0, mhB = 0;
    if (l < 9) {
        __half2 a = __float2half2_rn(__ldg(Mm + (size_t)eA * 9 + l));
        __half2 b = __float2half2_rn(__ldg(Mm + (size_t)eB * 9 + l));
        mhA = *reinterpret_cast<unsigned*>(&a);
        mhB = *reinterpret_cast<unsigned*>(&b);
    }

    // q rows: 192 halfs = 48 uint2; one component = 16 uint2 = 128B.
    const uint2* qjA = reinterpret_cast<const uint2*>(g_qh + (size_t)sA * 192) + l;
    const uint2* qiA = reinterpret_cast<const uint2*>(g_qh + (size_t)rA * 192) + l;
    const uint2* qjB = reinterpret_cast<const uint2*>(g_qh + (size_t)sB * 192) + l;
    const uint2* qiB = reinterpret_cast<const uint2*>(g_qh + (size_t)rB * 192) + l;

    uint2 jA0 = __ldg(qjA + 0), jA1 = __ldg(qjA + 16), jA2 = __ldg(qjA + 32);
    uint2 iA0 = __ldg(qiA + 0), iA1 = __ldg(qiA + 16), iA2 = __ldg(qiA + 32);
    uint2 jB0 = __ldg(qjB + 0), jB1 = __ldg(qjB + 16), jB2 = __ldg(qjB + 32);
    uint2 iB0 = __ldg(qiB + 0), iB1 = __ldg(qiB + 16), iB2 = __ldg(qiB + 32);

    float4 dA = pole_energy_h(mhA, jA0, jA1, jA2, iA0, iA1, iA2);
    {
        float* dst = out + (size_t)rA * 64 + 4 * l;
        asm volatile("red.global.add.v4.f32 [%0], {%1, %2, %3, %4};"
                     :: "l"(dst), "f"(dA.x), "f"(dA.y), "f"(dA.z), "f"(dA.w)
                     : "memory");
    }

    if (hasB) {
        float4 dB = pole_energy_h(mhB, jB0, jB1, jB2, iB0, iB1, iB2);
        float* dst = out + (size_t)rB * 64 + 4 * l;
        asm volatile("red.global.add.v4.f32 [%0], {%1, %2, %3, %4};"
                     :: "l"(dst), "f"(dB.x), "f"(dB.y), "f"(dB.z), "f"(dB.w)
                     : "memory");
    }
}

// ---------------------------------------------------------------------------
extern "C" void kernel_launch(void* const* d_in, const int* in_sizes, int n_in,
                              void* d_out, int out_size)
{
    const float* x         = (const float*)d_in[0];
    const float* vec       = (const float*)d_in[1];
    const int*   senders   = (const int*)  d_in[2];
    const int*   receivers = (const int*)  d_in[3];
    const float* im        = (const float*)d_in[4];
    const float* ln_scale  = (const float*)d_in[5];
    const float* ln_bias   = (const float*)d_in[6];
    const float* vln       = (const float*)d_in[7];
    const float* w1        = (const float*)d_in[8];
    const float* b1        = (const float*)d_in[9];
    const float* w2        = (const float*)d_in[10];
    const float* b2        = (const float*)d_in[11];

    int N = in_sizes[0] / CCH;
    int E = in_sizes[2];

    const int smem = (64 * 128 + 128 * 64 + K1_WARPS * 64 * NPW + K1_WARPS * NPW * 128)
                     * (int)sizeof(float);                       // 112 KB
    static bool attr_set = false;
    if (!attr_set) {
        cudaFuncSetAttribute(k_node, cudaFuncAttributeMaxDynamicSharedMemorySize, smem);
        attr_set = true;
    }
    k_node<<<K1_GRID, 32 * K1_WARPS, smem>>>(
        x, vec, ln_scale, ln_bias, vln, w1, b1, w2, b2, (float*)d_out, N);

    int ngroups = (E + 1) / 2;                    // 2 edges per 16-lane group
    long long tot = (long long)ngroups * 16;
    int eblocks = (int)((tot + 255) / 256);
    k_edge<<<eblocks, 256>>>(senders, receivers, im, (float*)d_out, E);
}